// round 12
// baseline (speedup 1.0000x reference)
#include <cuda_runtime.h>
#include <cuda_fp16.h>
#include <math.h>
#include <stdint.h>

// ---------------- problem constants ----------------
#define B_   8
#define N_   256
#define C_   3072
#define H_   8
#define HD_  384
#define FF_  12288
#define P_   32
#define NC_  (N_*C_)
#define BH_  (B_*H_)
#define QKV_SZ   (B_*N_*C_)
#define ATT_SZ   (B_*H_*N_*N_)
#define HBUF_SZ  (B_*N_*FF_)

// ---------------- device scratch ----------------
__device__ __align__(256) __half g_hq[QKV_SZ];
__device__ __align__(256) __half g_hk[QKV_SZ];
__device__ __align__(256) __half g_hvt[QKV_SZ];     // V^T: (BH, hd, N)
__device__ __align__(256) __half g_hattn2[ATT_SZ];
__device__ __align__(256) __half g_hctx[QKV_SZ];
__device__ __align__(256) __half g_hynh[QKV_SZ];
__device__ __align__(256) __half g_hh[HBUF_SZ];
__device__ __align__(256) __half g_hprojT[C_*C_];
__device__ __align__(256) __half g_hw1T[(long)C_*FF_];
__device__ __align__(256) __half g_hw2T[(long)C_*FF_];
__device__ float g_attn[ATT_SZ];
__device__ float g_y1[QKV_SZ];
__device__ float g_yn[QKV_SZ];
__device__ float g_y2[QKV_SZ];
__device__ float g_stats[B_*2];
__device__ double g_part[B_*32*2];

// ---------------- helpers ----------------
__device__ __forceinline__ float gelu_exact(float x) {
    return 0.5f * x * (1.0f + erff(x * 0.70710678118654752f));
}
__device__ __forceinline__ uint32_t smem_u32(const void* p) {
    return (uint32_t)__cvta_generic_to_shared(p);
}
__device__ __forceinline__ void cpa16(uint32_t dst, const void* src) {
    asm volatile("cp.async.cg.shared.global [%0], [%1], 16;\n" :: "r"(dst), "l"(src));
}
__device__ __forceinline__ void cp_commit() { asm volatile("cp.async.commit_group;\n"); }
template<int NN> __device__ __forceinline__ void cp_wait() {
    asm volatile("cp.async.wait_group %0;\n" :: "n"(NN));
}
__device__ __forceinline__ void ldsm_x4(uint32_t* r, uint32_t addr) {
    asm volatile("ldmatrix.sync.aligned.m8n8.x4.shared.b16 {%0,%1,%2,%3}, [%4];"
                 : "=r"(r[0]), "=r"(r[1]), "=r"(r[2]), "=r"(r[3]) : "r"(addr));
}
__device__ __forceinline__ void mma_f16(float c[4], uint32_t a0, uint32_t a1, uint32_t a2,
                                        uint32_t a3, uint32_t b0, uint32_t b1) {
    asm volatile(
        "mma.sync.aligned.m16n8k16.row.col.f32.f16.f16.f32 "
        "{%0,%1,%2,%3},{%4,%5,%6,%7},{%8,%9},{%0,%1,%2,%3};\n"
        : "+f"(c[0]), "+f"(c[1]), "+f"(c[2]), "+f"(c[3])
        : "r"(a0), "r"(a1), "r"(a2), "r"(a3), "r"(b0), "r"(b1));
}

// ================= 128x256 fp16 GEMM, 512 threads, 4-stage (QK) =================
#define A2SZ (128*144)
#define B2SZ (256*144)
#define STG2 (A2SZ + B2SZ)    // 55296
#define SMEM2 (4*STG2)        // 221184

template<int EPI, typename OutT>
__global__ void __launch_bounds__(512, 1)
hgemm256(const __half* __restrict__ A, const __half* __restrict__ Bm, OutT* __restrict__ C,
         int K, int lda, int ldb, int ldc,
         long sA, long sB, int zdiv, long sC1, long sC2,
         const float* __restrict__ bias, const float* __restrict__ resid)
{
    extern __shared__ char smem[];
    const uint32_t sbase = smem_u32(smem);

    int tid = threadIdx.x;
    int warp = tid >> 5, lane = tid & 31;
    int wm = warp >> 2, wn = warp & 3;     // 4x4 warp grid, 32x64 warp tile
    int z = blockIdx.z;
    const __half* Ab = A + (long)z * sA;
    const __half* Bb = Bm + (long)z * sB;
    long coff = (long)(z / zdiv) * sC1 + (long)(z % zdiv) * sC2;
    OutT* Cb = C + coff;
    int rowBlk = blockIdx.y * 128;
    int colBlk = blockIdx.x * 256;

    float acc[2][8][4];
    #pragma unroll
    for (int mi = 0; mi < 2; mi++)
        #pragma unroll
        for (int ni = 0; ni < 8; ni++)
            #pragma unroll
            for (int r = 0; r < 4; r++) acc[mi][ni][r] = 0.0f;

    uint32_t aoff = (uint32_t)(((wm*32 + (lane & 15)) * 72 + ((lane >> 4) << 3)) * 2);
    uint32_t boff = (uint32_t)(((wn*64 + (lane & 7) + ((lane >> 4) << 3)) * 72 + (lane & 8)) * 2);

    auto load_chunk = [&](int ck, int s) {
        uint32_t ab = sbase + s*STG2;
        uint32_t bb = ab + A2SZ;
        const __half* Ag = Ab + (long)rowBlk * lda + ck*64;
        const __half* Bg = Bb + (long)colBlk * ldb + ck*64;
        #pragma unroll
        for (int it = 0; it < 2; it++) {
            int idx = tid + it*512;
            int row = idx >> 3, gq = idx & 7;
            cpa16(ab + row*144 + gq*16, Ag + (long)row*lda + gq*8);
        }
        #pragma unroll
        for (int it = 0; it < 4; it++) {
            int idx = tid + it*512;
            int row = idx >> 3, gq = idx & 7;
            cpa16(bb + row*144 + gq*16, Bg + (long)row*ldb + gq*8);
        }
        cp_commit();
    };

    int nc = K >> 6;
    load_chunk(0, 0);
    if (nc > 1) load_chunk(1, 1); else cp_commit();
    if (nc > 2) load_chunk(2, 2); else cp_commit();

    for (int c = 0; c < nc; c++) {
        cp_wait<2>();
        __syncthreads();
        if (c + 3 < nc) load_chunk(c + 3, (c + 3) & 3);
        else            cp_commit();

        uint32_t As = sbase + (c & 3)*STG2;
        uint32_t Bs = As + A2SZ;

        uint32_t af[2][2][4], bf[2][4][4];
        #pragma unroll
        for (int mi = 0; mi < 2; mi++) ldsm_x4(af[0][mi], As + aoff + mi*2304u);
        #pragma unroll
        for (int j = 0; j < 4; j++)    ldsm_x4(bf[0][j],  Bs + boff + j*2304u);

        #pragma unroll
        for (int ki = 0; ki < 4; ki++) {
            int cur = ki & 1;
            if (ki < 3) {
                int kk2 = (ki + 1) * 16 * 2;
                #pragma unroll
                for (int mi = 0; mi < 2; mi++) ldsm_x4(af[cur^1][mi], As + aoff + mi*2304u + kk2);
                #pragma unroll
                for (int j = 0; j < 4; j++)    ldsm_x4(bf[cur^1][j],  Bs + boff + j*2304u + kk2);
            }
            #pragma unroll
            for (int mi = 0; mi < 2; mi++)
                #pragma unroll
                for (int ni = 0; ni < 8; ni++)
                    mma_f16(acc[mi][ni], af[cur][mi][0], af[cur][mi][1],
                            af[cur][mi][2], af[cur][mi][3],
                            bf[cur][ni >> 1][(ni & 1)*2], bf[cur][ni >> 1][(ni & 1)*2 + 1]);
        }
    }

    __syncthreads();
    int g = lane >> 2, t4 = lane & 3;
    #pragma unroll
    for (int mi = 0; mi < 2; mi++) {
        #pragma unroll
        for (int ni = 0; ni < 8; ni++) {
            int r0 = rowBlk + wm*32 + mi*16 + g;
            int c0 = colBlk + wn*64 + ni*8 + 2*t4;
            float v0 = acc[mi][ni][0], v1 = acc[mi][ni][1];
            float v2 = acc[mi][ni][2], v3 = acc[mi][ni][3];
            if (EPI == 0 || EPI == 2) {
                *(__half2*)&((__half*)Cb)[(long)r0*ldc + c0]     = __floats2half2_rn(v0, v1);
                *(__half2*)&((__half*)Cb)[(long)(r0+8)*ldc + c0] = __floats2half2_rn(v2, v3);
            } else {
                *(float2*)&((float*)Cb)[(long)r0*ldc + c0]     = make_float2(v0, v1);
                *(float2*)&((float*)Cb)[(long)(r0+8)*ldc + c0] = make_float2(v2, v3);
            }
        }
    }
}

// ================= 128x192 fp16 GEMM, 384 threads, 2-stage, 2 CTA/SM =================
#define A4SZ (128*144)        // 18432
#define B4SZ (192*144)        // 27648
#define STG4 (A4SZ + B4SZ)    // 46080
#define SMEM4 (2*STG4)        // 92160 (x2 CTAs = 184320 <= 227KB)

// warp grid 4(m) x 3(n); warp tile 32(m) x 64(n); acc 2x8x4 = 64 regs
// EPI: 0 plain->half, 2 bias+gelu->half, 3 bias+resid->float
template<int EPI, typename OutT>
__global__ void __launch_bounds__(384, 2)
hgemm192(const __half* __restrict__ A, const __half* __restrict__ Bm, OutT* __restrict__ C,
         int K, int lda, int ldb, int ldc,
         long sA, long sB, int zdiv, long sC1, long sC2,
         const float* __restrict__ bias, const float* __restrict__ resid)
{
    extern __shared__ char smem[];
    const uint32_t sbase = smem_u32(smem);

    int tid = threadIdx.x;
    int warp = tid >> 5, lane = tid & 31;
    int wm = warp / 3, wn = warp % 3;
    int z = blockIdx.z;
    const __half* Ab = A + (long)z * sA;
    const __half* Bb = Bm + (long)z * sB;
    long coff = (long)(z / zdiv) * sC1 + (long)(z % zdiv) * sC2;
    OutT* Cb = C + coff;
    int rowBlk = blockIdx.y * 128;
    int colBlk = blockIdx.x * 192;

    float acc[2][8][4];
    #pragma unroll
    for (int mi = 0; mi < 2; mi++)
        #pragma unroll
        for (int ni = 0; ni < 8; ni++)
            #pragma unroll
            for (int r = 0; r < 4; r++) acc[mi][ni][r] = 0.0f;

    uint32_t aoff = (uint32_t)(((wm*32 + (lane & 15)) * 72 + ((lane >> 4) << 3)) * 2);
    uint32_t boff = (uint32_t)(((wn*64 + (lane & 7) + ((lane >> 4) << 3)) * 72 + (lane & 8)) * 2);

    auto load_chunk = [&](int ck, int s) {
        uint32_t ab = sbase + s*STG4;
        uint32_t bb = ab + A4SZ;
        const __half* Ag = Ab + (long)rowBlk * lda + ck*64;
        const __half* Bg = Bb + (long)colBlk * ldb + ck*64;
        #pragma unroll
        for (int it = 0; it < 3; it++) {           // A: 1024 granules over 384 thr
            int idx = tid + it*384;
            if (idx < 1024) {
                int row = idx >> 3, gq = idx & 7;
                cpa16(ab + row*144 + gq*16, Ag + (long)row*lda + gq*8);
            }
        }
        #pragma unroll
        for (int it = 0; it < 4; it++) {           // B: 1536 granules = 4*384 exactly
            int idx = tid + it*384;
            int row = idx >> 3, gq = idx & 7;
            cpa16(bb + row*144 + gq*16, Bg + (long)row*ldb + gq*8);
        }
        cp_commit();
    };

    int nc = K >> 6;
    load_chunk(0, 0);

    for (int c = 0; c < nc; c++) {
        int s = c & 1;
        if (c + 1 < nc) { load_chunk(c + 1, s ^ 1); cp_wait<1>(); }
        else            { cp_wait<0>(); }
        __syncthreads();

        uint32_t As = sbase + s*STG4;
        uint32_t Bs = As + A4SZ;

        uint32_t af[2][2][4], bf[2][4][4];
        #pragma unroll
        for (int mi = 0; mi < 2; mi++) ldsm_x4(af[0][mi], As + aoff + mi*2304u);
        #pragma unroll
        for (int j = 0; j < 4; j++)    ldsm_x4(bf[0][j],  Bs + boff + j*2304u);

        #pragma unroll
        for (int ki = 0; ki < 4; ki++) {
            int cur = ki & 1;
            if (ki < 3) {
                int kk2 = (ki + 1) * 32;
                #pragma unroll
                for (int mi = 0; mi < 2; mi++) ldsm_x4(af[cur^1][mi], As + aoff + mi*2304u + kk2);
                #pragma unroll
                for (int j = 0; j < 4; j++)    ldsm_x4(bf[cur^1][j],  Bs + boff + j*2304u + kk2);
            }
            #pragma unroll
            for (int mi = 0; mi < 2; mi++)
                #pragma unroll
                for (int ni = 0; ni < 8; ni++)
                    mma_f16(acc[mi][ni], af[cur][mi][0], af[cur][mi][1],
                            af[cur][mi][2], af[cur][mi][3],
                            bf[cur][ni >> 1][(ni & 1)*2], bf[cur][ni >> 1][(ni & 1)*2 + 1]);
        }
        __syncthreads();
    }

    int g = lane >> 2, t4 = lane & 3;
    #pragma unroll
    for (int mi = 0; mi < 2; mi++) {
        #pragma unroll
        for (int ni = 0; ni < 8; ni++) {
            int r0 = rowBlk + wm*32 + mi*16 + g;
            int c0 = colBlk + wn*64 + ni*8 + 2*t4;
            float v0 = acc[mi][ni][0], v1 = acc[mi][ni][1];
            float v2 = acc[mi][ni][2], v3 = acc[mi][ni][3];
            if (EPI >= 2) {
                float b0 = bias[c0], b1 = bias[c0+1];
                v0 += b0; v1 += b1; v2 += b0; v3 += b1;
            }
            if (EPI == 2) {
                v0 = gelu_exact(v0); v1 = gelu_exact(v1);
                v2 = gelu_exact(v2); v3 = gelu_exact(v3);
            }
            if (EPI == 3) {
                const float2 ra = *(const float2*)&resid[coff + (long)r0*ldc + c0];
                const float2 rb = *(const float2*)&resid[coff + (long)(r0+8)*ldc + c0];
                v0 += ra.x; v1 += ra.y; v2 += rb.x; v3 += rb.y;
            }
            if (EPI == 0 || EPI == 2) {
                *(__half2*)&((__half*)Cb)[(long)r0*ldc + c0]     = __floats2half2_rn(v0, v1);
                *(__half2*)&((__half*)Cb)[(long)(r0+8)*ldc + c0] = __floats2half2_rn(v2, v3);
            } else {
                *(float2*)&((float*)Cb)[(long)r0*ldc + c0]     = make_float2(v0, v1);
                *(float2*)&((float*)Cb)[(long)(r0+8)*ldc + c0] = make_float2(v2, v3);
            }
        }
    }
}

// ---------------- fast transpose fp32 -> fp16, half2 stores ----------------
__global__ void transpose_h2(const float* __restrict__ src, __half* __restrict__ dst,
                             int Rr, int Ccol)
{
    __shared__ float t[64][33];
    int c0 = blockIdx.x * 32, r0 = blockIdx.y * 64;
    int tx = threadIdx.x, ty = threadIdx.y;
    int x = c0 + tx;
    #pragma unroll
    for (int j = ty; j < 64; j += 8)
        t[j][tx] = src[(long)(r0 + j) * Ccol + x];
    __syncthreads();
    #pragma unroll
    for (int j = ty; j < 32; j += 8) {
        __half2 h = __floats2half2_rn(t[2*tx][j], t[2*tx+1][j]);
        *(__half2*)&dst[(long)(c0 + j) * Rr + r0 + 2*tx] = h;
    }
}

// ---------------- fused conv QKV, 4-position register blocking ----------------
__global__ void __launch_bounds__(256, 2) conv_qkv(const float* __restrict__ x,
                                                   const float* __restrict__ qw,
                                                   const float* __restrict__ kw,
                                                   const float* __restrict__ vw)
{
    __shared__ float sp[3][P_+2][P_+2];
    __shared__ float swq[81], swk[81], swv[81];
    int tid = threadIdx.x;
    int patch = blockIdx.x;
    int b = patch >> 8;
    int n = patch & 255;
    const float* xp = x + (long)patch * C_;

    if (tid < 81) { swq[tid] = qw[tid]; swk[tid] = kw[tid]; swv[tid] = vw[tid]; }
    for (int i = tid; i < 3*(P_+2)*(P_+2); i += 256)
        ((float*)sp)[i] = 0.0f;
    __syncthreads();
    for (int i = tid; i < C_; i += 256) {
        int ch = i >> 10;
        int s  = i & 1023;
        sp[ch][(s >> 5)+1][(s & 31)+1] = xp[i];
    }
    __syncthreads();

    int pos0 = tid * 4;
    int yy = pos0 >> 5, xx = pos0 & 31;
    float aq[3][4], ak[3][4], av[3][4];
    #pragma unroll
    for (int o = 0; o < 3; o++)
        #pragma unroll
        for (int p = 0; p < 4; p++) { aq[o][p] = 0.f; ak[o][p] = 0.f; av[o][p] = 0.f; }

    #pragma unroll
    for (int i = 0; i < 3; i++) {
        #pragma unroll
        for (int dy = 0; dy < 3; dy++) {
            float r[6];
            #pragma unroll
            for (int t = 0; t < 6; t++) r[t] = sp[i][yy+dy][xx+t];
            #pragma unroll
            for (int dx = 0; dx < 3; dx++) {
                int wi = i*9 + dy*3 + dx;
                float wq0 = swq[wi], wq1 = swq[27+wi], wq2 = swq[54+wi];
                float wk0 = swk[wi], wk1 = swk[27+wi], wk2 = swk[54+wi];
                float wv0 = swv[wi], wv1 = swv[27+wi], wv2 = swv[54+wi];
                #pragma unroll
                for (int p = 0; p < 4; p++) {
                    float val = r[dx + p];
                    aq[0][p] = fmaf(val, wq0, aq[0][p]);
                    aq[1][p] = fmaf(val, wq1, aq[1][p]);
                    aq[2][p] = fmaf(val, wq2, aq[2][p]);
                    ak[0][p] = fmaf(val, wk0, ak[0][p]);
                    ak[1][p] = fmaf(val, wk1, ak[1][p]);
                    ak[2][p] = fmaf(val, wk2, ak[2][p]);
                    av[0][p] = fmaf(val, wv0, av[0][p]);
                    av[1][p] = fmaf(val, wv1, av[1][p]);
                    av[2][p] = fmaf(val, wv2, av[2][p]);
                }
            }
        }
    }

    #pragma unroll
    for (int o = 0; o < 3; o++) {
        int c0 = o*1024 + pos0;
        int h = c0 / HD_;
        int d = c0 - h*HD_;
        long bh = (long)(b*H_ + h);
        long base = (bh*N_ + n)*HD_ + d;
        *(__half2*)&g_hq[base]   = __floats2half2_rn(aq[o][0], aq[o][1]);
        *(__half2*)&g_hq[base+2] = __floats2half2_rn(aq[o][2], aq[o][3]);
        *(__half2*)&g_hk[base]   = __floats2half2_rn(ak[o][0], ak[o][1]);
        *(__half2*)&g_hk[base+2] = __floats2half2_rn(ak[o][2], ak[o][3]);
        #pragma unroll
        for (int p = 0; p < 4; p++)
            g_hvt[(bh*HD_ + d + p)*N_ + n] = __float2half_rn(av[o][p]);
    }
}

// ---------------- fused softmax + re-attention + BN -> fp16 ----------------
__global__ void __launch_bounds__(256) softmax_reatten(
    const float* __restrict__ attn, __half* __restrict__ attn2,
    const float* __restrict__ w,  const float* __restrict__ rb,
    const float* __restrict__ g,  const float* __restrict__ bta,
    const float* __restrict__ mean, const float* __restrict__ var)
{
    __shared__ float sp[8][256];
    __shared__ float sw[64], sscale[8], sshift[8];
    int tid = threadIdx.x;
    int h = tid >> 5, lane = tid & 31;
    if (tid < 64) sw[tid] = w[tid];
    if (tid < 8) {
        float inv = rsqrtf(var[tid] + 1e-5f);
        float gi = g[tid] * inv;
        sscale[tid] = gi;
        sshift[tid] = bta[tid] + (rb[tid] - mean[tid]) * gi;
    }
    int b = blockIdx.x >> 8, n = blockIdx.x & 255;
    const float scale = 0.051031036307982884f;
    const float* row = attn + (((long)(b*H_ + h))*N_ + n)*N_;

    float v[8];
    #pragma unroll
    for (int j = 0; j < 8; j++) v[j] = row[lane + j*32] * scale;
    float m = v[0];
    #pragma unroll
    for (int j = 1; j < 8; j++) m = fmaxf(m, v[j]);
    #pragma unroll
    for (int o = 16; o > 0; o >>= 1) m = fmaxf(m, __shfl_xor_sync(0xffffffffu, m, o));
    float s = 0.0f;
    float e[8];
    #pragma unroll
    for (int j = 0; j < 8; j++) { e[j] = __expf(v[j] - m); s += e[j]; }
    #pragma unroll
    for (int o = 16; o > 0; o >>= 1) s += __shfl_xor_sync(0xffffffffu, s, o);
    float inv = 1.0f / s;
    #pragma unroll
    for (int j = 0; j < 8; j++) sp[h][lane + j*32] = e[j] * inv;
    __syncthreads();

    float in[8];
    #pragma unroll
    for (int i = 0; i < 8; i++) in[i] = sp[i][tid];
    #pragma unroll
    for (int o = 0; o < 8; o++) {
        float acc = 0.0f;
        #pragma unroll
        for (int i = 0; i < 8; i++) acc = fmaf(sw[o*8 + i], in[i], acc);
        attn2[(((long)(b*H_ + o))*N_ + n)*N_ + tid] =
            __float2half_rn(acc * sscale[o] + sshift[o]);
    }
}

// ---------------- LayerNorm: two-level stats ----------------
__global__ void ln_part(const float* __restrict__ y)
{
    __shared__ double rs[8], rq[8];
    int b = blockIdx.y, seg = blockIdx.x;
    const float* p = y + (long)b * NC_ + (long)seg * (NC_/32);
    double s = 0.0, q = 0.0;
    for (int i = threadIdx.x; i < NC_/32; i += 256) {
        double v = (double)p[i];
        s += v; q += v * v;
    }
    #pragma unroll
    for (int o = 16; o > 0; o >>= 1) {
        s += __shfl_xor_sync(0xffffffffu, s, o);
        q += __shfl_xor_sync(0xffffffffu, q, o);
    }
    int lane = threadIdx.x & 31, wid = threadIdx.x >> 5;
    if (lane == 0) { rs[wid] = s; rq[wid] = q; }
    __syncthreads();
    if (threadIdx.x == 0) {
        double S = 0.0, Q = 0.0;
        #pragma unroll
        for (int i = 0; i < 8; i++) { S += rs[i]; Q += rq[i]; }
        g_part[(b*32 + seg)*2]     = S;
        g_part[(b*32 + seg)*2 + 1] = Q;
    }
}

__global__ void ln_fin(float* __restrict__ stats)
{
    int b = blockIdx.x, t = threadIdx.x;
    double s = g_part[(b*32 + t)*2];
    double q = g_part[(b*32 + t)*2 + 1];
    #pragma unroll
    for (int o = 16; o > 0; o >>= 1) {
        s += __shfl_xor_sync(0xffffffffu, s, o);
        q += __shfl_xor_sync(0xffffffffu, q, o);
    }
    if (t == 0) {
        double mu  = s / (double)NC_;
        double var = q / (double)NC_ - mu * mu;
        stats[b*2]   = (float)mu;
        stats[b*2+1] = (float)rsqrt(var + 1e-5);
    }
}

__global__ void ln_apply_dual(const float* __restrict__ y, const float* __restrict__ stats,
                              const float* __restrict__ g, const float* __restrict__ beta,
                              float* __restrict__ outf, __half* __restrict__ outh)
{
    long i = (long)blockIdx.x * blockDim.x + threadIdx.x;
    int b = (int)(i / NC_);
    int r = (int)(i % NC_);
    float v = (y[i] - stats[b*2]) * stats[b*2+1] * g[r] + beta[r];
    outf[i] = v;
    outh[i] = __float2half_rn(v);
}

__global__ void ln_apply(const float* __restrict__ y, const float* __restrict__ stats,
                         const float* __restrict__ g, const float* __restrict__ beta,
                         float* __restrict__ out)
{
    long i = (long)blockIdx.x * blockDim.x + threadIdx.x;
    int b = (int)(i / NC_);
    int r = (int)(i % NC_);
    out[i] = (y[i] - stats[b*2]) * stats[b*2+1] * g[r] + beta[r];
}

// ---------------- launch ----------------
extern "C" void kernel_launch(void* const* d_in, const int* in_sizes, int n_in,
                              void* d_out, int out_size)
{
    const float* x        = (const float*)d_in[0];
    const float* qconv_w  = (const float*)d_in[1];
    const float* kconv_w  = (const float*)d_in[2];
    const float* vconv_w  = (const float*)d_in[3];
    const float* reat_w   = (const float*)d_in[4];
    const float* reat_b   = (const float*)d_in[5];
    const float* bn_gamma = (const float*)d_in[6];
    const float* bn_beta  = (const float*)d_in[7];
    const float* bn_mean  = (const float*)d_in[8];
    const float* bn_var   = (const float*)d_in[9];
    const float* proj_w   = (const float*)d_in[10];
    const float* proj_b   = (const float*)d_in[11];
    const float* ln_g     = (const float*)d_in[12];
    const float* ln_b     = (const float*)d_in[13];
    const float* ff_w1    = (const float*)d_in[14];
    const float* ff_b1    = (const float*)d_in[15];
    const float* ff_w2    = (const float*)d_in[16];
    const float* ff_b2    = (const float*)d_in[17];
    float* out = (float*)d_out;

    __half *pq, *pk, *pvt, *pattn2, *pctx, *pynh, *ph, *pprojT, *pw1T, *pw2T;
    float *pattn, *py1, *pyn, *py2, *pstats;
    cudaGetSymbolAddress((void**)&pq,     g_hq);
    cudaGetSymbolAddress((void**)&pk,     g_hk);
    cudaGetSymbolAddress((void**)&pvt,    g_hvt);
    cudaGetSymbolAddress((void**)&pattn2, g_hattn2);
    cudaGetSymbolAddress((void**)&pctx,   g_hctx);
    cudaGetSymbolAddress((void**)&pynh,   g_hynh);
    cudaGetSymbolAddress((void**)&ph,     g_hh);
    cudaGetSymbolAddress((void**)&pprojT, g_hprojT);
    cudaGetSymbolAddress((void**)&pw1T,   g_hw1T);
    cudaGetSymbolAddress((void**)&pw2T,   g_hw2T);
    cudaGetSymbolAddress((void**)&pattn,  g_attn);
    cudaGetSymbolAddress((void**)&py1,    g_y1);
    cudaGetSymbolAddress((void**)&pyn,    g_yn);
    cudaGetSymbolAddress((void**)&py2,    g_y2);
    cudaGetSymbolAddress((void**)&pstats, g_stats);

    cudaFuncSetAttribute(hgemm256<1,float>,  cudaFuncAttributeMaxDynamicSharedMemorySize, SMEM2);
    cudaFuncSetAttribute(hgemm192<0,__half>, cudaFuncAttributeMaxDynamicSharedMemorySize, SMEM4);
    cudaFuncSetAttribute(hgemm192<2,__half>, cudaFuncAttributeMaxDynamicSharedMemorySize, SMEM4);
    cudaFuncSetAttribute(hgemm192<3,float>,  cudaFuncAttributeMaxDynamicSharedMemorySize, SMEM4);

    // 1. fused conv QKV  (launch 0)
    conv_qkv<<<B_*N_, 256>>>(x, qconv_w, kconv_w, vconv_w);

    // 2. S = Q K^T  (launch 1)
    hgemm256<1,float><<<dim3(1,2,BH_), 512, SMEM2>>>(pq, pk, pattn,
        HD_, HD_, HD_, N_, (long)N_*HD_, (long)N_*HD_, 1, 65536L, 0L, nullptr, nullptr);

    // 3. fused softmax + re-attention (launch 2)
    softmax_reatten<<<B_*N_, 256>>>(pattn, pattn2, reat_w, reat_b,
                                    bn_gamma, bn_beta, bn_mean, bn_var);

    // 4. ctx = attn2 @ V (launch 3)
    hgemm192<0,__half><<<dim3(2,2,BH_), 384, SMEM4>>>(pattn2, pvt, pctx,
        N_, N_, N_, C_, 65536L, (long)HD_*N_, H_, (long)N_*C_, (long)HD_, nullptr, nullptr);

    // 5. proj weight transpose (launch 4)
    {
        dim3 blk(32, 8);
        transpose_h2<<<dim3(C_/32, C_/64), blk>>>(proj_w, pprojT, C_, C_);
    }

    // 6. y1 = x + ctx @ proj_w + proj_b  (launch 5 — ncu target)
    hgemm192<3,float><<<dim3(C_/192, (B_*N_)/128), 384, SMEM4>>>(pctx, pprojT, py1,
        C_, C_, C_, C_, 0L, 0L, 1, 0L, 0L, proj_b, x);

    // 7. FFN weight transposes
    {
        dim3 blk(32, 8);
        transpose_h2<<<dim3(FF_/32, C_/64), blk>>>(ff_w1, pw1T, C_, FF_);
        transpose_h2<<<dim3(C_/32, FF_/64), blk>>>(ff_w2, pw2T, FF_, C_);
    }

    // 8. LN1
    ln_part<<<dim3(32, B_), 256>>>(py1);
    ln_fin<<<B_, 32>>>(pstats);
    ln_apply_dual<<<QKV_SZ/256, 256>>>(py1, pstats, ln_g, ln_b, pyn, pynh);

    // 9. h = gelu(yn @ ff_w1 + b1)
    hgemm192<2,__half><<<dim3(FF_/192, (B_*N_)/128), 384, SMEM4>>>(pynh, pw1T, ph,
        C_, C_, C_, FF_, 0L, 0L, 1, 0L, 0L, ff_b1, nullptr);

    // 10. y2 = yn + h @ ff_w2 + b2
    hgemm192<3,float><<<dim3(C_/192, (B_*N_)/128), 384, SMEM4>>>(ph, pw2T, py2,
        FF_, FF_, FF_, C_, 0L, 0L, 1, 0L, 0L, ff_b2, pyn);

    // 11. LN2 -> out
    ln_part<<<dim3(32, B_), 256>>>(py2);
    ln_fin<<<B_, 32>>>(pstats);
    ln_apply<<<QKV_SZ/256, 256>>>(py2, pstats, ln_g, ln_b, out);
}

// round 13
// speedup vs baseline: 1.3494x; 1.3494x over previous
#include <cuda_runtime.h>
#include <cuda_fp16.h>
#include <math.h>
#include <stdint.h>

// ---------------- problem constants ----------------
#define B_   8
#define N_   256
#define C_   3072
#define H_   8
#define HD_  384
#define FF_  12288
#define P_   32
#define NC_  (N_*C_)
#define BH_  (B_*H_)
#define QKV_SZ   (B_*N_*C_)
#define ATT_SZ   (B_*H_*N_*N_)
#define HBUF_SZ  (B_*N_*FF_)

// ---------------- device scratch ----------------
__device__ __align__(256) __half g_hq[QKV_SZ];
__device__ __align__(256) __half g_hk[QKV_SZ];
__device__ __align__(256) __half g_hvt[QKV_SZ];     // V^T: (BH, hd, N)
__device__ __align__(256) __half g_hattn2[ATT_SZ];
__device__ __align__(256) __half g_hctx[QKV_SZ];
__device__ __align__(256) __half g_hynh[QKV_SZ];
__device__ __align__(256) __half g_hh[HBUF_SZ];
__device__ __align__(256) __half g_hprojT[C_*C_];
__device__ __align__(256) __half g_hw1T[(long)C_*FF_];
__device__ __align__(256) __half g_hw2T[(long)C_*FF_];
__device__ float g_attn[ATT_SZ];
__device__ float g_y1[QKV_SZ];
__device__ float g_yn[QKV_SZ];
__device__ float g_y2[QKV_SZ];
__device__ float g_stats[B_*2];
__device__ double g_part[B_*32*2];

// ---------------- helpers ----------------
__device__ __forceinline__ float gelu_exact(float x) {
    return 0.5f * x * (1.0f + erff(x * 0.70710678118654752f));
}
__device__ __forceinline__ uint32_t smem_u32(const void* p) {
    return (uint32_t)__cvta_generic_to_shared(p);
}
__device__ __forceinline__ void cpa16(uint32_t dst, const void* src) {
    asm volatile("cp.async.cg.shared.global [%0], [%1], 16;\n" :: "r"(dst), "l"(src));
}
__device__ __forceinline__ void cp_commit() { asm volatile("cp.async.commit_group;\n"); }
template<int NN> __device__ __forceinline__ void cp_wait() {
    asm volatile("cp.async.wait_group %0;\n" :: "n"(NN));
}
__device__ __forceinline__ void ldsm_x4(uint32_t* r, uint32_t addr) {
    asm volatile("ldmatrix.sync.aligned.m8n8.x4.shared.b16 {%0,%1,%2,%3}, [%4];"
                 : "=r"(r[0]), "=r"(r[1]), "=r"(r[2]), "=r"(r[3]) : "r"(addr));
}
__device__ __forceinline__ void mma_f16(float c[4], uint32_t a0, uint32_t a1, uint32_t a2,
                                        uint32_t a3, uint32_t b0, uint32_t b1) {
    asm volatile(
        "mma.sync.aligned.m16n8k16.row.col.f32.f16.f16.f32 "
        "{%0,%1,%2,%3},{%4,%5,%6,%7},{%8,%9},{%0,%1,%2,%3};\n"
        : "+f"(c[0]), "+f"(c[1]), "+f"(c[2]), "+f"(c[3])
        : "r"(a0), "r"(a1), "r"(a2), "r"(a3), "r"(b0), "r"(b1));
}

// ================= 128x256 fp16 GEMM, 512 threads, 4-stage (QK) =================
#define A2SZ (128*144)
#define B2SZ (256*144)
#define STG2 (A2SZ + B2SZ)    // 55296
#define SMEM2 (4*STG2)        // 221184

template<int EPI, typename OutT>
__global__ void __launch_bounds__(512, 1)
hgemm256(const __half* __restrict__ A, const __half* __restrict__ Bm, OutT* __restrict__ C,
         int K, int lda, int ldb, int ldc,
         long sA, long sB, int zdiv, long sC1, long sC2,
         const float* __restrict__ bias, const float* __restrict__ resid)
{
    extern __shared__ char smem[];
    const uint32_t sbase = smem_u32(smem);

    int tid = threadIdx.x;
    int warp = tid >> 5, lane = tid & 31;
    int wm = warp >> 2, wn = warp & 3;     // 4x4 warp grid, 32x64 warp tile
    int z = blockIdx.z;
    const __half* Ab = A + (long)z * sA;
    const __half* Bb = Bm + (long)z * sB;
    long coff = (long)(z / zdiv) * sC1 + (long)(z % zdiv) * sC2;
    OutT* Cb = C + coff;
    int rowBlk = blockIdx.y * 128;
    int colBlk = blockIdx.x * 256;

    float acc[2][8][4];
    #pragma unroll
    for (int mi = 0; mi < 2; mi++)
        #pragma unroll
        for (int ni = 0; ni < 8; ni++)
            #pragma unroll
            for (int r = 0; r < 4; r++) acc[mi][ni][r] = 0.0f;

    uint32_t aoff = (uint32_t)(((wm*32 + (lane & 15)) * 72 + ((lane >> 4) << 3)) * 2);
    uint32_t boff = (uint32_t)(((wn*64 + (lane & 7) + ((lane >> 4) << 3)) * 72 + (lane & 8)) * 2);

    auto load_chunk = [&](int ck, int s) {
        uint32_t ab = sbase + s*STG2;
        uint32_t bb = ab + A2SZ;
        const __half* Ag = Ab + (long)rowBlk * lda + ck*64;
        const __half* Bg = Bb + (long)colBlk * ldb + ck*64;
        #pragma unroll
        for (int it = 0; it < 2; it++) {
            int idx = tid + it*512;
            int row = idx >> 3, gq = idx & 7;
            cpa16(ab + row*144 + gq*16, Ag + (long)row*lda + gq*8);
        }
        #pragma unroll
        for (int it = 0; it < 4; it++) {
            int idx = tid + it*512;
            int row = idx >> 3, gq = idx & 7;
            cpa16(bb + row*144 + gq*16, Bg + (long)row*ldb + gq*8);
        }
        cp_commit();
    };

    int nc = K >> 6;
    load_chunk(0, 0);
    if (nc > 1) load_chunk(1, 1); else cp_commit();
    if (nc > 2) load_chunk(2, 2); else cp_commit();

    for (int c = 0; c < nc; c++) {
        cp_wait<2>();
        __syncthreads();
        if (c + 3 < nc) load_chunk(c + 3, (c + 3) & 3);
        else            cp_commit();

        uint32_t As = sbase + (c & 3)*STG2;
        uint32_t Bs = As + A2SZ;

        uint32_t af[2][2][4], bf[2][4][4];
        #pragma unroll
        for (int mi = 0; mi < 2; mi++) ldsm_x4(af[0][mi], As + aoff + mi*2304u);
        #pragma unroll
        for (int j = 0; j < 4; j++)    ldsm_x4(bf[0][j],  Bs + boff + j*2304u);

        #pragma unroll
        for (int ki = 0; ki < 4; ki++) {
            int cur = ki & 1;
            if (ki < 3) {
                int kk2 = (ki + 1) * 16 * 2;
                #pragma unroll
                for (int mi = 0; mi < 2; mi++) ldsm_x4(af[cur^1][mi], As + aoff + mi*2304u + kk2);
                #pragma unroll
                for (int j = 0; j < 4; j++)    ldsm_x4(bf[cur^1][j],  Bs + boff + j*2304u + kk2);
            }
            #pragma unroll
            for (int mi = 0; mi < 2; mi++)
                #pragma unroll
                for (int ni = 0; ni < 8; ni++)
                    mma_f16(acc[mi][ni], af[cur][mi][0], af[cur][mi][1],
                            af[cur][mi][2], af[cur][mi][3],
                            bf[cur][ni >> 1][(ni & 1)*2], bf[cur][ni >> 1][(ni & 1)*2 + 1]);
        }
    }

    __syncthreads();
    int g = lane >> 2, t4 = lane & 3;
    #pragma unroll
    for (int mi = 0; mi < 2; mi++) {
        #pragma unroll
        for (int ni = 0; ni < 8; ni++) {
            int r0 = rowBlk + wm*32 + mi*16 + g;
            int c0 = colBlk + wn*64 + ni*8 + 2*t4;
            float v0 = acc[mi][ni][0], v1 = acc[mi][ni][1];
            float v2 = acc[mi][ni][2], v3 = acc[mi][ni][3];
            if (EPI == 0 || EPI == 2) {
                *(__half2*)&((__half*)Cb)[(long)r0*ldc + c0]     = __floats2half2_rn(v0, v1);
                *(__half2*)&((__half*)Cb)[(long)(r0+8)*ldc + c0] = __floats2half2_rn(v2, v3);
            } else {
                *(float2*)&((float*)Cb)[(long)r0*ldc + c0]     = make_float2(v0, v1);
                *(float2*)&((float*)Cb)[(long)(r0+8)*ldc + c0] = make_float2(v2, v3);
            }
        }
    }
}

// ================= 128x192 fp16 GEMM, 384 threads, 4-stage, 1 CTA/SM =================
#define A4SZ (128*144)        // 18432
#define B4SZ (192*144)        // 27648
#define STG4 (A4SZ + B4SZ)    // 46080
#define SMEM4 (4*STG4)        // 184320

// EPI: 0 plain->half, 2 bias+gelu->half, 3 bias+resid->float
template<int EPI, typename OutT>
__global__ void __launch_bounds__(384, 1)
hgemm192(const __half* __restrict__ A, const __half* __restrict__ Bm, OutT* __restrict__ C,
         int K, int lda, int ldb, int ldc,
         long sA, long sB, int zdiv, long sC1, long sC2,
         const float* __restrict__ bias, const float* __restrict__ resid)
{
    extern __shared__ char smem[];
    const uint32_t sbase = smem_u32(smem);

    int tid = threadIdx.x;
    int warp = tid >> 5, lane = tid & 31;
    int wm = warp / 3, wn = warp % 3;      // 4x3 warp grid, 32x64 warp tile
    int z = blockIdx.z;
    const __half* Ab = A + (long)z * sA;
    const __half* Bb = Bm + (long)z * sB;
    long coff = (long)(z / zdiv) * sC1 + (long)(z % zdiv) * sC2;
    OutT* Cb = C + coff;
    int rowBlk = blockIdx.y * 128;
    int colBlk = blockIdx.x * 192;

    float acc[2][8][4];
    #pragma unroll
    for (int mi = 0; mi < 2; mi++)
        #pragma unroll
        for (int ni = 0; ni < 8; ni++)
            #pragma unroll
            for (int r = 0; r < 4; r++) acc[mi][ni][r] = 0.0f;

    uint32_t aoff = (uint32_t)(((wm*32 + (lane & 15)) * 72 + ((lane >> 4) << 3)) * 2);
    uint32_t boff = (uint32_t)(((wn*64 + (lane & 7) + ((lane >> 4) << 3)) * 72 + (lane & 8)) * 2);

    auto load_chunk = [&](int ck, int s) {
        uint32_t ab = sbase + s*STG4;
        uint32_t bb = ab + A4SZ;
        const __half* Ag = Ab + (long)rowBlk * lda + ck*64;
        const __half* Bg = Bb + (long)colBlk * ldb + ck*64;
        #pragma unroll
        for (int it = 0; it < 3; it++) {           // A: 1024 granules over 384 thr
            int idx = tid + it*384;
            if (idx < 1024) {
                int row = idx >> 3, gq = idx & 7;
                cpa16(ab + row*144 + gq*16, Ag + (long)row*lda + gq*8);
            }
        }
        #pragma unroll
        for (int it = 0; it < 4; it++) {           // B: 1536 granules = 4*384 exactly
            int idx = tid + it*384;
            int row = idx >> 3, gq = idx & 7;
            cpa16(bb + row*144 + gq*16, Bg + (long)row*ldb + gq*8);
        }
        cp_commit();
    };

    int nc = K >> 6;
    load_chunk(0, 0);
    if (nc > 1) load_chunk(1, 1); else cp_commit();
    if (nc > 2) load_chunk(2, 2); else cp_commit();

    for (int c = 0; c < nc; c++) {
        cp_wait<2>();
        __syncthreads();
        if (c + 3 < nc) load_chunk(c + 3, (c + 3) & 3);
        else            cp_commit();

        uint32_t As = sbase + (c & 3)*STG4;
        uint32_t Bs = As + A4SZ;

        uint32_t af[2][2][4], bf[2][4][4];
        #pragma unroll
        for (int mi = 0; mi < 2; mi++) ldsm_x4(af[0][mi], As + aoff + mi*2304u);
        #pragma unroll
        for (int j = 0; j < 4; j++)    ldsm_x4(bf[0][j],  Bs + boff + j*2304u);

        #pragma unroll
        for (int ki = 0; ki < 4; ki++) {
            int cur = ki & 1;
            if (ki < 3) {
                int kk2 = (ki + 1) * 32;
                #pragma unroll
                for (int mi = 0; mi < 2; mi++) ldsm_x4(af[cur^1][mi], As + aoff + mi*2304u + kk2);
                #pragma unroll
                for (int j = 0; j < 4; j++)    ldsm_x4(bf[cur^1][j],  Bs + boff + j*2304u + kk2);
            }
            #pragma unroll
            for (int mi = 0; mi < 2; mi++)
                #pragma unroll
                for (int ni = 0; ni < 8; ni++)
                    mma_f16(acc[mi][ni], af[cur][mi][0], af[cur][mi][1],
                            af[cur][mi][2], af[cur][mi][3],
                            bf[cur][ni >> 1][(ni & 1)*2], bf[cur][ni >> 1][(ni & 1)*2 + 1]);
        }
    }

    __syncthreads();
    int g = lane >> 2, t4 = lane & 3;
    #pragma unroll
    for (int mi = 0; mi < 2; mi++) {
        #pragma unroll
        for (int ni = 0; ni < 8; ni++) {
            int r0 = rowBlk + wm*32 + mi*16 + g;
            int c0 = colBlk + wn*64 + ni*8 + 2*t4;
            float v0 = acc[mi][ni][0], v1 = acc[mi][ni][1];
            float v2 = acc[mi][ni][2], v3 = acc[mi][ni][3];
            if (EPI >= 2) {
                float b0 = bias[c0], b1 = bias[c0+1];
                v0 += b0; v1 += b1; v2 += b0; v3 += b1;
            }
            if (EPI == 2) {
                v0 = gelu_exact(v0); v1 = gelu_exact(v1);
                v2 = gelu_exact(v2); v3 = gelu_exact(v3);
            }
            if (EPI == 3) {
                const float2 ra = *(const float2*)&resid[coff + (long)r0*ldc + c0];
                const float2 rb = *(const float2*)&resid[coff + (long)(r0+8)*ldc + c0];
                v0 += ra.x; v1 += ra.y; v2 += rb.x; v3 += rb.y;
            }
            if (EPI == 0 || EPI == 2) {
                *(__half2*)&((__half*)Cb)[(long)r0*ldc + c0]     = __floats2half2_rn(v0, v1);
                *(__half2*)&((__half*)Cb)[(long)(r0+8)*ldc + c0] = __floats2half2_rn(v2, v3);
            } else {
                *(float2*)&((float*)Cb)[(long)r0*ldc + c0]     = make_float2(v0, v1);
                *(float2*)&((float*)Cb)[(long)(r0+8)*ldc + c0] = make_float2(v2, v3);
            }
        }
    }
}

// ---------------- fast transpose fp32 -> fp16, half2 stores ----------------
__global__ void transpose_h2(const float* __restrict__ src, __half* __restrict__ dst,
                             int Rr, int Ccol)
{
    __shared__ float t[64][33];
    int c0 = blockIdx.x * 32, r0 = blockIdx.y * 64;
    int tx = threadIdx.x, ty = threadIdx.y;
    int x = c0 + tx;
    #pragma unroll
    for (int j = ty; j < 64; j += 8)
        t[j][tx] = src[(long)(r0 + j) * Ccol + x];
    __syncthreads();
    #pragma unroll
    for (int j = ty; j < 32; j += 8) {
        __half2 h = __floats2half2_rn(t[2*tx][j], t[2*tx+1][j]);
        *(__half2*)&dst[(long)(c0 + j) * Rr + r0 + 2*tx] = h;
    }
}

// ---------------- fused conv QKV, 4-position register blocking ----------------
__global__ void __launch_bounds__(256, 2) conv_qkv(const float* __restrict__ x,
                                                   const float* __restrict__ qw,
                                                   const float* __restrict__ kw,
                                                   const float* __restrict__ vw)
{
    __shared__ float sp[3][P_+2][P_+2];
    __shared__ float swq[81], swk[81], swv[81];
    int tid = threadIdx.x;
    int patch = blockIdx.x;
    int b = patch >> 8;
    int n = patch & 255;
    const float* xp = x + (long)patch * C_;

    if (tid < 81) { swq[tid] = qw[tid]; swk[tid] = kw[tid]; swv[tid] = vw[tid]; }
    for (int i = tid; i < 3*(P_+2)*(P_+2); i += 256)
        ((float*)sp)[i] = 0.0f;
    __syncthreads();
    // x is contiguous per patch: load as float4 (768 float4s over 256 threads)
    {
        const float4* xp4 = (const float4*)xp;
        #pragma unroll
        for (int it = 0; it < 3; it++) {
            int i4 = tid + it*256;
            float4 v = xp4[i4];
            int i = i4 * 4;
            int ch = i >> 10;
            int s  = i & 1023;
            int yy = s >> 5, xx = s & 31;
            // 4 consecutive positions stay in one row (xx multiple of 4, <= 28)
            sp[ch][yy+1][xx+1] = v.x;
            sp[ch][yy+1][xx+2] = v.y;
            sp[ch][yy+1][xx+3] = v.z;
            sp[ch][yy+1][xx+4] = v.w;
        }
    }
    __syncthreads();

    int pos0 = tid * 4;
    int yy = pos0 >> 5, xx = pos0 & 31;
    float aq[3][4], ak[3][4], av[3][4];
    #pragma unroll
    for (int o = 0; o < 3; o++)
        #pragma unroll
        for (int p = 0; p < 4; p++) { aq[o][p] = 0.f; ak[o][p] = 0.f; av[o][p] = 0.f; }

    #pragma unroll
    for (int i = 0; i < 3; i++) {
        #pragma unroll
        for (int dy = 0; dy < 3; dy++) {
            float r[6];
            #pragma unroll
            for (int t = 0; t < 6; t++) r[t] = sp[i][yy+dy][xx+t];
            #pragma unroll
            for (int dx = 0; dx < 3; dx++) {
                int wi = i*9 + dy*3 + dx;
                float wq0 = swq[wi], wq1 = swq[27+wi], wq2 = swq[54+wi];
                float wk0 = swk[wi], wk1 = swk[27+wi], wk2 = swk[54+wi];
                float wv0 = swv[wi], wv1 = swv[27+wi], wv2 = swv[54+wi];
                #pragma unroll
                for (int p = 0; p < 4; p++) {
                    float val = r[dx + p];
                    aq[0][p] = fmaf(val, wq0, aq[0][p]);
                    aq[1][p] = fmaf(val, wq1, aq[1][p]);
                    aq[2][p] = fmaf(val, wq2, aq[2][p]);
                    ak[0][p] = fmaf(val, wk0, ak[0][p]);
                    ak[1][p] = fmaf(val, wk1, ak[1][p]);
                    ak[2][p] = fmaf(val, wk2, ak[2][p]);
                    av[0][p] = fmaf(val, wv0, av[0][p]);
                    av[1][p] = fmaf(val, wv1, av[1][p]);
                    av[2][p] = fmaf(val, wv2, av[2][p]);
                }
            }
        }
    }

    #pragma unroll
    for (int o = 0; o < 3; o++) {
        int c0 = o*1024 + pos0;
        int h = c0 / HD_;
        int d = c0 - h*HD_;
        long bh = (long)(b*H_ + h);
        long base = (bh*N_ + n)*HD_ + d;
        *(__half2*)&g_hq[base]   = __floats2half2_rn(aq[o][0], aq[o][1]);
        *(__half2*)&g_hq[base+2] = __floats2half2_rn(aq[o][2], aq[o][3]);
        *(__half2*)&g_hk[base]   = __floats2half2_rn(ak[o][0], ak[o][1]);
        *(__half2*)&g_hk[base+2] = __floats2half2_rn(ak[o][2], ak[o][3]);
        #pragma unroll
        for (int p = 0; p < 4; p++)
            g_hvt[(bh*HD_ + d + p)*N_ + n] = __float2half_rn(av[o][p]);
    }
}

// ---------------- fused softmax + re-attention + BN -> fp16 ----------------
__global__ void __launch_bounds__(256) softmax_reatten(
    const float* __restrict__ attn, __half* __restrict__ attn2,
    const float* __restrict__ w,  const float* __restrict__ rb,
    const float* __restrict__ g,  const float* __restrict__ bta,
    const float* __restrict__ mean, const float* __restrict__ var)
{
    __shared__ float sp[8][256];
    __shared__ float sw[64], sscale[8], sshift[8];
    int tid = threadIdx.x;
    int h = tid >> 5, lane = tid & 31;
    if (tid < 64) sw[tid] = w[tid];
    if (tid < 8) {
        float inv = rsqrtf(var[tid] + 1e-5f);
        float gi = g[tid] * inv;
        sscale[tid] = gi;
        sshift[tid] = bta[tid] + (rb[tid] - mean[tid]) * gi;
    }
    int b = blockIdx.x >> 8, n = blockIdx.x & 255;
    const float scale = 0.051031036307982884f;
    const float* row = attn + (((long)(b*H_ + h))*N_ + n)*N_;

    float v[8];
    #pragma unroll
    for (int j = 0; j < 8; j++) v[j] = row[lane + j*32] * scale;
    float m = v[0];
    #pragma unroll
    for (int j = 1; j < 8; j++) m = fmaxf(m, v[j]);
    #pragma unroll
    for (int o = 16; o > 0; o >>= 1) m = fmaxf(m, __shfl_xor_sync(0xffffffffu, m, o));
    float s = 0.0f;
    float e[8];
    #pragma unroll
    for (int j = 0; j < 8; j++) { e[j] = __expf(v[j] - m); s += e[j]; }
    #pragma unroll
    for (int o = 16; o > 0; o >>= 1) s += __shfl_xor_sync(0xffffffffu, s, o);
    float inv = 1.0f / s;
    #pragma unroll
    for (int j = 0; j < 8; j++) sp[h][lane + j*32] = e[j] * inv;
    __syncthreads();

    float in[8];
    #pragma unroll
    for (int i = 0; i < 8; i++) in[i] = sp[i][tid];
    #pragma unroll
    for (int o = 0; o < 8; o++) {
        float acc = 0.0f;
        #pragma unroll
        for (int i = 0; i < 8; i++) acc = fmaf(sw[o*8 + i], in[i], acc);
        attn2[(((long)(b*H_ + o))*N_ + n)*N_ + tid] =
            __float2half_rn(acc * sscale[o] + sshift[o]);
    }
}

// ---------------- LayerNorm: two-level stats ----------------
__global__ void ln_part(const float* __restrict__ y)
{
    __shared__ double rs[8], rq[8];
    int b = blockIdx.y, seg = blockIdx.x;
    const float4* p = (const float4*)(y + (long)b * NC_ + (long)seg * (NC_/32));
    double s = 0.0, q = 0.0;
    for (int i = threadIdx.x; i < NC_/128; i += 256) {
        float4 v = p[i];
        s += (double)v.x + (double)v.y + (double)v.z + (double)v.w;
        q += (double)v.x*v.x + (double)v.y*v.y + (double)v.z*v.z + (double)v.w*v.w;
    }
    #pragma unroll
    for (int o = 16; o > 0; o >>= 1) {
        s += __shfl_xor_sync(0xffffffffu, s, o);
        q += __shfl_xor_sync(0xffffffffu, q, o);
    }
    int lane = threadIdx.x & 31, wid = threadIdx.x >> 5;
    if (lane == 0) { rs[wid] = s; rq[wid] = q; }
    __syncthreads();
    if (threadIdx.x == 0) {
        double S = 0.0, Q = 0.0;
        #pragma unroll
        for (int i = 0; i < 8; i++) { S += rs[i]; Q += rq[i]; }
        g_part[(b*32 + seg)*2]     = S;
        g_part[(b*32 + seg)*2 + 1] = Q;
    }
}

__global__ void ln_fin(float* __restrict__ stats)
{
    int b = blockIdx.x, t = threadIdx.x;
    double s = g_part[(b*32 + t)*2];
    double q = g_part[(b*32 + t)*2 + 1];
    #pragma unroll
    for (int o = 16; o > 0; o >>= 1) {
        s += __shfl_xor_sync(0xffffffffu, s, o);
        q += __shfl_xor_sync(0xffffffffu, q, o);
    }
    if (t == 0) {
        double mu  = s / (double)NC_;
        double var = q / (double)NC_ - mu * mu;
        stats[b*2]   = (float)mu;
        stats[b*2+1] = (float)rsqrt(var + 1e-5);
    }
}

// vectorized: each thread does 4 consecutive elements
__global__ void ln_apply_dual(const float* __restrict__ y, const float* __restrict__ stats,
                              const float* __restrict__ g, const float* __restrict__ beta,
                              float* __restrict__ outf, __half* __restrict__ outh)
{
    long i4 = (long)blockIdx.x * blockDim.x + threadIdx.x;
    long i = i4 * 4;
    int b = (int)(i / NC_);
    int r = (int)(i % NC_);
    float mu = stats[b*2], iv = stats[b*2+1];
    float4 yv = *(const float4*)&y[i];
    const float4 gv = *(const float4*)&g[r];
    const float4 bv = *(const float4*)&beta[r];
    float4 o;
    o.x = (yv.x - mu) * iv * gv.x + bv.x;
    o.y = (yv.y - mu) * iv * gv.y + bv.y;
    o.z = (yv.z - mu) * iv * gv.z + bv.z;
    o.w = (yv.w - mu) * iv * gv.w + bv.w;
    *(float4*)&outf[i] = o;
    __half2 h0 = __floats2half2_rn(o.x, o.y);
    __half2 h1 = __floats2half2_rn(o.z, o.w);
    *(__half2*)&outh[i]   = h0;
    *(__half2*)&outh[i+2] = h1;
}

__global__ void ln_apply(const float* __restrict__ y, const float* __restrict__ stats,
                         const float* __restrict__ g, const float* __restrict__ beta,
                         float* __restrict__ out)
{
    long i4 = (long)blockIdx.x * blockDim.x + threadIdx.x;
    long i = i4 * 4;
    int b = (int)(i / NC_);
    int r = (int)(i % NC_);
    float mu = stats[b*2], iv = stats[b*2+1];
    float4 yv = *(const float4*)&y[i];
    const float4 gv = *(const float4*)&g[r];
    const float4 bv = *(const float4*)&beta[r];
    float4 o;
    o.x = (yv.x - mu) * iv * gv.x + bv.x;
    o.y = (yv.y - mu) * iv * gv.y + bv.y;
    o.z = (yv.z - mu) * iv * gv.z + bv.z;
    o.w = (yv.w - mu) * iv * gv.w + bv.w;
    *(float4*)&out[i] = o;
}

// ---------------- launch ----------------
extern "C" void kernel_launch(void* const* d_in, const int* in_sizes, int n_in,
                              void* d_out, int out_size)
{
    const float* x        = (const float*)d_in[0];
    const float* qconv_w  = (const float*)d_in[1];
    const float* kconv_w  = (const float*)d_in[2];
    const float* vconv_w  = (const float*)d_in[3];
    const float* reat_w   = (const float*)d_in[4];
    const float* reat_b   = (const float*)d_in[5];
    const float* bn_gamma = (const float*)d_in[6];
    const float* bn_beta  = (const float*)d_in[7];
    const float* bn_mean  = (const float*)d_in[8];
    const float* bn_var   = (const float*)d_in[9];
    const float* proj_w   = (const float*)d_in[10];
    const float* proj_b   = (const float*)d_in[11];
    const float* ln_g     = (const float*)d_in[12];
    const float* ln_b     = (const float*)d_in[13];
    const float* ff_w1    = (const float*)d_in[14];
    const float* ff_b1    = (const float*)d_in[15];
    const float* ff_w2    = (const float*)d_in[16];
    const float* ff_b2    = (const float*)d_in[17];
    float* out = (float*)d_out;

    __half *pq, *pk, *pvt, *pattn2, *pctx, *pynh, *ph, *pprojT, *pw1T, *pw2T;
    float *pattn, *py1, *pyn, *py2, *pstats;
    cudaGetSymbolAddress((void**)&pq,     g_hq);
    cudaGetSymbolAddress((void**)&pk,     g_hk);
    cudaGetSymbolAddress((void**)&pvt,    g_hvt);
    cudaGetSymbolAddress((void**)&pattn2, g_hattn2);
    cudaGetSymbolAddress((void**)&pctx,   g_hctx);
    cudaGetSymbolAddress((void**)&pynh,   g_hynh);
    cudaGetSymbolAddress((void**)&ph,     g_hh);
    cudaGetSymbolAddress((void**)&pprojT, g_hprojT);
    cudaGetSymbolAddress((void**)&pw1T,   g_hw1T);
    cudaGetSymbolAddress((void**)&pw2T,   g_hw2T);
    cudaGetSymbolAddress((void**)&pattn,  g_attn);
    cudaGetSymbolAddress((void**)&py1,    g_y1);
    cudaGetSymbolAddress((void**)&pyn,    g_yn);
    cudaGetSymbolAddress((void**)&py2,    g_y2);
    cudaGetSymbolAddress((void**)&pstats, g_stats);

    cudaFuncSetAttribute(hgemm256<1,float>,  cudaFuncAttributeMaxDynamicSharedMemorySize, SMEM2);
    cudaFuncSetAttribute(hgemm192<0,__half>, cudaFuncAttributeMaxDynamicSharedMemorySize, SMEM4);
    cudaFuncSetAttribute(hgemm192<2,__half>, cudaFuncAttributeMaxDynamicSharedMemorySize, SMEM4);
    cudaFuncSetAttribute(hgemm192<3,float>,  cudaFuncAttributeMaxDynamicSharedMemorySize, SMEM4);

    // 1. fused conv QKV  (launch 0)
    conv_qkv<<<B_*N_, 256>>>(x, qconv_w, kconv_w, vconv_w);

    // 2. S = Q K^T  (launch 1)
    hgemm256<1,float><<<dim3(1,2,BH_), 512, SMEM2>>>(pq, pk, pattn,
        HD_, HD_, HD_, N_, (long)N_*HD_, (long)N_*HD_, 1, 65536L, 0L, nullptr, nullptr);

    // 3. fused softmax + re-attention (launch 2)
    softmax_reatten<<<B_*N_, 256>>>(pattn, pattn2, reat_w, reat_b,
                                    bn_gamma, bn_beta, bn_mean, bn_var);

    // 4. ctx = attn2 @ V (launch 3)
    hgemm192<0,__half><<<dim3(2,2,BH_), 384, SMEM4>>>(pattn2, pvt, pctx,
        N_, N_, N_, C_, 65536L, (long)HD_*N_, H_, (long)N_*C_, (long)HD_, nullptr, nullptr);

    // 5. proj weight transpose (launch 4)
    {
        dim3 blk(32, 8);
        transpose_h2<<<dim3(C_/32, C_/64), blk>>>(proj_w, pprojT, C_, C_);
    }

    // 6. y1 = x + ctx @ proj_w + proj_b  (launch 5 — ncu target)
    hgemm192<3,float><<<dim3(C_/192, (B_*N_)/128), 384, SMEM4>>>(pctx, pprojT, py1,
        C_, C_, C_, C_, 0L, 0L, 1, 0L, 0L, proj_b, x);

    // 7. FFN weight transposes
    {
        dim3 blk(32, 8);
        transpose_h2<<<dim3(FF_/32, C_/64), blk>>>(ff_w1, pw1T, C_, FF_);
        transpose_h2<<<dim3(C_/32, FF_/64), blk>>>(ff_w2, pw2T, FF_, C_);
    }

    // 8. LN1
    ln_part<<<dim3(32, B_), 256>>>(py1);
    ln_fin<<<B_, 32>>>(pstats);
    ln_apply_dual<<<QKV_SZ/1024, 256>>>(py1, pstats, ln_g, ln_b, pyn, pynh);

    // 9. h = gelu(yn @ ff_w1 + b1)
    hgemm192<2,__half><<<dim3(FF_/192, (B_*N_)/128), 384, SMEM4>>>(pynh, pw1T, ph,
        C_, C_, C_, FF_, 0L, 0L, 1, 0L, 0L, ff_b1, nullptr);

    // 10. y2 = yn + h @ ff_w2 + b2
    hgemm192<3,float><<<dim3(C_/192, (B_*N_)/128), 384, SMEM4>>>(ph, pw2T, py2,
        FF_, FF_, FF_, C_, 0L, 0L, 1, 0L, 0L, ff_b2, pyn);

    // 11. LN2 -> out
    ln_part<<<dim3(32, B_), 256>>>(py2);
    ln_fin<<<B_, 32>>>(pstats);
    ln_apply<<<QKV_SZ/1024, 256>>>(py2, pstats, ln_g, ln_b, out);
}

// round 14
// speedup vs baseline: 1.3530x; 1.0027x over previous
#include <cuda_runtime.h>
#include <cuda_fp16.h>
#include <math.h>
#include <stdint.h>

// ---------------- problem constants ----------------
#define B_   8
#define N_   256
#define C_   3072
#define H_   8
#define HD_  384
#define FF_  12288
#define P_   32
#define NC_  (N_*C_)
#define BH_  (B_*H_)
#define QKV_SZ   (B_*N_*C_)
#define ATT_SZ   (B_*H_*N_*N_)
#define HBUF_SZ  (B_*N_*FF_)

// ---------------- device scratch ----------------
__device__ __align__(256) __half g_hq[QKV_SZ];
__device__ __align__(256) __half g_hk[QKV_SZ];
__device__ __align__(256) __half g_hvt[QKV_SZ];     // V^T: (BH, hd, N)
__device__ __align__(256) __half g_hattn2[ATT_SZ];
__device__ __align__(256) __half g_hctx[QKV_SZ];
__device__ __align__(256) __half g_hynh[QKV_SZ];
__device__ __align__(256) __half g_hh[HBUF_SZ];
__device__ __align__(256) __half g_hprojT[C_*C_];
__device__ __align__(256) __half g_hw1T[(long)C_*FF_];
__device__ __align__(256) __half g_hw2T[(long)C_*FF_];
__device__ float g_attn[ATT_SZ];
__device__ float g_y1[QKV_SZ];
__device__ float g_yn[QKV_SZ];
__device__ float g_y2[QKV_SZ];
__device__ float g_stats[B_*2];
__device__ double g_part[B_*32*2];

// ---------------- helpers ----------------
__device__ __forceinline__ float gelu_exact(float x) {
    return 0.5f * x * (1.0f + erff(x * 0.70710678118654752f));
}
__device__ __forceinline__ uint32_t smem_u32(const void* p) {
    return (uint32_t)__cvta_generic_to_shared(p);
}
__device__ __forceinline__ void cpa16(uint32_t dst, const void* src) {
    asm volatile("cp.async.cg.shared.global [%0], [%1], 16;\n" :: "r"(dst), "l"(src));
}
__device__ __forceinline__ void cp_commit() { asm volatile("cp.async.commit_group;\n"); }
template<int NN> __device__ __forceinline__ void cp_wait() {
    asm volatile("cp.async.wait_group %0;\n" :: "n"(NN));
}
__device__ __forceinline__ void ldsm_x4(uint32_t* r, uint32_t addr) {
    asm volatile("ldmatrix.sync.aligned.m8n8.x4.shared.b16 {%0,%1,%2,%3}, [%4];"
                 : "=r"(r[0]), "=r"(r[1]), "=r"(r[2]), "=r"(r[3]) : "r"(addr));
}
__device__ __forceinline__ void mma_f16(float c[4], uint32_t a0, uint32_t a1, uint32_t a2,
                                        uint32_t a3, uint32_t b0, uint32_t b1) {
    asm volatile(
        "mma.sync.aligned.m16n8k16.row.col.f32.f16.f16.f32 "
        "{%0,%1,%2,%3},{%4,%5,%6,%7},{%8,%9},{%0,%1,%2,%3};\n"
        : "+f"(c[0]), "+f"(c[1]), "+f"(c[2]), "+f"(c[3])
        : "r"(a0), "r"(a1), "r"(a2), "r"(a3), "r"(b0), "r"(b1));
}

// ================= 128x256 fp16 GEMM, 512 threads, 4-stage (QK) =================
#define A2SZ (128*144)
#define B2SZ (256*144)
#define STG2 (A2SZ + B2SZ)    // 55296
#define SMEM2 (4*STG2)        // 221184

template<int EPI, typename OutT>
__global__ void __launch_bounds__(512, 1)
hgemm256(const __half* __restrict__ A, const __half* __restrict__ Bm, OutT* __restrict__ C,
         int K, int lda, int ldb, int ldc,
         long sA, long sB, int zdiv, long sC1, long sC2,
         const float* __restrict__ bias, const float* __restrict__ resid)
{
    extern __shared__ char smem[];
    const uint32_t sbase = smem_u32(smem);

    int tid = threadIdx.x;
    int warp = tid >> 5, lane = tid & 31;
    int wm = warp >> 2, wn = warp & 3;     // 4x4 warp grid, 32x64 warp tile
    int z = blockIdx.z;
    const __half* Ab = A + (long)z * sA;
    const __half* Bb = Bm + (long)z * sB;
    long coff = (long)(z / zdiv) * sC1 + (long)(z % zdiv) * sC2;
    OutT* Cb = C + coff;
    int rowBlk = blockIdx.y * 128;
    int colBlk = blockIdx.x * 256;

    float acc[2][8][4];
    #pragma unroll
    for (int mi = 0; mi < 2; mi++)
        #pragma unroll
        for (int ni = 0; ni < 8; ni++)
            #pragma unroll
            for (int r = 0; r < 4; r++) acc[mi][ni][r] = 0.0f;

    uint32_t aoff = (uint32_t)(((wm*32 + (lane & 15)) * 72 + ((lane >> 4) << 3)) * 2);
    uint32_t boff = (uint32_t)(((wn*64 + (lane & 7) + ((lane >> 4) << 3)) * 72 + (lane & 8)) * 2);

    auto load_chunk = [&](int ck, int s) {
        uint32_t ab = sbase + s*STG2;
        uint32_t bb = ab + A2SZ;
        const __half* Ag = Ab + (long)rowBlk * lda + ck*64;
        const __half* Bg = Bb + (long)colBlk * ldb + ck*64;
        #pragma unroll
        for (int it = 0; it < 2; it++) {
            int idx = tid + it*512;
            int row = idx >> 3, gq = idx & 7;
            cpa16(ab + row*144 + gq*16, Ag + (long)row*lda + gq*8);
        }
        #pragma unroll
        for (int it = 0; it < 4; it++) {
            int idx = tid + it*512;
            int row = idx >> 3, gq = idx & 7;
            cpa16(bb + row*144 + gq*16, Bg + (long)row*ldb + gq*8);
        }
        cp_commit();
    };

    int nc = K >> 6;
    load_chunk(0, 0);
    if (nc > 1) load_chunk(1, 1); else cp_commit();
    if (nc > 2) load_chunk(2, 2); else cp_commit();

    for (int c = 0; c < nc; c++) {
        cp_wait<2>();
        __syncthreads();
        if (c + 3 < nc) load_chunk(c + 3, (c + 3) & 3);
        else            cp_commit();

        uint32_t As = sbase + (c & 3)*STG2;
        uint32_t Bs = As + A2SZ;

        uint32_t af[2][2][4], bf[2][4][4];
        #pragma unroll
        for (int mi = 0; mi < 2; mi++) ldsm_x4(af[0][mi], As + aoff + mi*2304u);
        #pragma unroll
        for (int j = 0; j < 4; j++)    ldsm_x4(bf[0][j],  Bs + boff + j*2304u);

        #pragma unroll
        for (int ki = 0; ki < 4; ki++) {
            int cur = ki & 1;
            if (ki < 3) {
                int kk2 = (ki + 1) * 16 * 2;
                #pragma unroll
                for (int mi = 0; mi < 2; mi++) ldsm_x4(af[cur^1][mi], As + aoff + mi*2304u + kk2);
                #pragma unroll
                for (int j = 0; j < 4; j++)    ldsm_x4(bf[cur^1][j],  Bs + boff + j*2304u + kk2);
            }
            #pragma unroll
            for (int mi = 0; mi < 2; mi++)
                #pragma unroll
                for (int ni = 0; ni < 8; ni++)
                    mma_f16(acc[mi][ni], af[cur][mi][0], af[cur][mi][1],
                            af[cur][mi][2], af[cur][mi][3],
                            bf[cur][ni >> 1][(ni & 1)*2], bf[cur][ni >> 1][(ni & 1)*2 + 1]);
        }
    }

    __syncthreads();
    int g = lane >> 2, t4 = lane & 3;
    #pragma unroll
    for (int mi = 0; mi < 2; mi++) {
        #pragma unroll
        for (int ni = 0; ni < 8; ni++) {
            int r0 = rowBlk + wm*32 + mi*16 + g;
            int c0 = colBlk + wn*64 + ni*8 + 2*t4;
            float v0 = acc[mi][ni][0], v1 = acc[mi][ni][1];
            float v2 = acc[mi][ni][2], v3 = acc[mi][ni][3];
            if (EPI == 0 || EPI == 2) {
                *(__half2*)&((__half*)Cb)[(long)r0*ldc + c0]     = __floats2half2_rn(v0, v1);
                *(__half2*)&((__half*)Cb)[(long)(r0+8)*ldc + c0] = __floats2half2_rn(v2, v3);
            } else {
                *(float2*)&((float*)Cb)[(long)r0*ldc + c0]     = make_float2(v0, v1);
                *(float2*)&((float*)Cb)[(long)(r0+8)*ldc + c0] = make_float2(v2, v3);
            }
        }
    }
}

// ================= 128x192 fp16 GEMM, 384 threads, 4-stage (AV) =================
#define A4SZ (128*144)        // 18432
#define B4SZ (192*144)        // 27648
#define STG4 (A4SZ + B4SZ)    // 46080
#define SMEM4 (4*STG4)        // 184320

template<int EPI, typename OutT>
__global__ void __launch_bounds__(384, 1)
hgemm192(const __half* __restrict__ A, const __half* __restrict__ Bm, OutT* __restrict__ C,
         int K, int lda, int ldb, int ldc,
         long sA, long sB, int zdiv, long sC1, long sC2,
         const float* __restrict__ bias, const float* __restrict__ resid)
{
    extern __shared__ char smem[];
    const uint32_t sbase = smem_u32(smem);

    int tid = threadIdx.x;
    int warp = tid >> 5, lane = tid & 31;
    int wm = warp / 3, wn = warp % 3;      // 4x3 warp grid, 32x64 warp tile
    int z = blockIdx.z;
    const __half* Ab = A + (long)z * sA;
    const __half* Bb = Bm + (long)z * sB;
    long coff = (long)(z / zdiv) * sC1 + (long)(z % zdiv) * sC2;
    OutT* Cb = C + coff;
    int rowBlk = blockIdx.y * 128;
    int colBlk = blockIdx.x * 192;

    float acc[2][8][4];
    #pragma unroll
    for (int mi = 0; mi < 2; mi++)
        #pragma unroll
        for (int ni = 0; ni < 8; ni++)
            #pragma unroll
            for (int r = 0; r < 4; r++) acc[mi][ni][r] = 0.0f;

    uint32_t aoff = (uint32_t)(((wm*32 + (lane & 15)) * 72 + ((lane >> 4) << 3)) * 2);
    uint32_t boff = (uint32_t)(((wn*64 + (lane & 7) + ((lane >> 4) << 3)) * 72 + (lane & 8)) * 2);

    auto load_chunk = [&](int ck, int s) {
        uint32_t ab = sbase + s*STG4;
        uint32_t bb = ab + A4SZ;
        const __half* Ag = Ab + (long)rowBlk * lda + ck*64;
        const __half* Bg = Bb + (long)colBlk * ldb + ck*64;
        #pragma unroll
        for (int it = 0; it < 3; it++) {
            int idx = tid + it*384;
            if (idx < 1024) {
                int row = idx >> 3, gq = idx & 7;
                cpa16(ab + row*144 + gq*16, Ag + (long)row*lda + gq*8);
            }
        }
        #pragma unroll
        for (int it = 0; it < 4; it++) {
            int idx = tid + it*384;
            int row = idx >> 3, gq = idx & 7;
            cpa16(bb + row*144 + gq*16, Bg + (long)row*ldb + gq*8);
        }
        cp_commit();
    };

    int nc = K >> 6;
    load_chunk(0, 0);
    if (nc > 1) load_chunk(1, 1); else cp_commit();
    if (nc > 2) load_chunk(2, 2); else cp_commit();

    for (int c = 0; c < nc; c++) {
        cp_wait<2>();
        __syncthreads();
        if (c + 3 < nc) load_chunk(c + 3, (c + 3) & 3);
        else            cp_commit();

        uint32_t As = sbase + (c & 3)*STG4;
        uint32_t Bs = As + A4SZ;

        uint32_t af[2][2][4], bf[2][4][4];
        #pragma unroll
        for (int mi = 0; mi < 2; mi++) ldsm_x4(af[0][mi], As + aoff + mi*2304u);
        #pragma unroll
        for (int j = 0; j < 4; j++)    ldsm_x4(bf[0][j],  Bs + boff + j*2304u);

        #pragma unroll
        for (int ki = 0; ki < 4; ki++) {
            int cur = ki & 1;
            if (ki < 3) {
                int kk2 = (ki + 1) * 32;
                #pragma unroll
                for (int mi = 0; mi < 2; mi++) ldsm_x4(af[cur^1][mi], As + aoff + mi*2304u + kk2);
                #pragma unroll
                for (int j = 0; j < 4; j++)    ldsm_x4(bf[cur^1][j],  Bs + boff + j*2304u + kk2);
            }
            #pragma unroll
            for (int mi = 0; mi < 2; mi++)
                #pragma unroll
                for (int ni = 0; ni < 8; ni++)
                    mma_f16(acc[mi][ni], af[cur][mi][0], af[cur][mi][1],
                            af[cur][mi][2], af[cur][mi][3],
                            bf[cur][ni >> 1][(ni & 1)*2], bf[cur][ni >> 1][(ni & 1)*2 + 1]);
        }
    }

    __syncthreads();
    int g = lane >> 2, t4 = lane & 3;
    #pragma unroll
    for (int mi = 0; mi < 2; mi++) {
        #pragma unroll
        for (int ni = 0; ni < 8; ni++) {
            int r0 = rowBlk + wm*32 + mi*16 + g;
            int c0 = colBlk + wn*64 + ni*8 + 2*t4;
            float v0 = acc[mi][ni][0], v1 = acc[mi][ni][1];
            float v2 = acc[mi][ni][2], v3 = acc[mi][ni][3];
            if (EPI >= 2) {
                float b0 = bias[c0], b1 = bias[c0+1];
                v0 += b0; v1 += b1; v2 += b0; v3 += b1;
            }
            if (EPI == 2) {
                v0 = gelu_exact(v0); v1 = gelu_exact(v1);
                v2 = gelu_exact(v2); v3 = gelu_exact(v3);
            }
            if (EPI == 3) {
                const float2 ra = *(const float2*)&resid[coff + (long)r0*ldc + c0];
                const float2 rb = *(const float2*)&resid[coff + (long)(r0+8)*ldc + c0];
                v0 += ra.x; v1 += ra.y; v2 += rb.x; v3 += rb.y;
            }
            if (EPI == 0 || EPI == 2) {
                *(__half2*)&((__half*)Cb)[(long)r0*ldc + c0]     = __floats2half2_rn(v0, v1);
                *(__half2*)&((__half*)Cb)[(long)(r0+8)*ldc + c0] = __floats2half2_rn(v2, v3);
            } else {
                *(float2*)&((float*)Cb)[(long)r0*ldc + c0]     = make_float2(v0, v1);
                *(float2*)&((float*)Cb)[(long)(r0+8)*ldc + c0] = make_float2(v2, v3);
            }
        }
    }
}

// ================= 128x192 fp16 GEMM, 512 threads (4x4 warps, 32x48 tiles) =================
// 4-stage, 1 CTA/SM, 16 warps = 4 warps/SMSP. EPI: 2 bias+gelu->half, 3 bias+resid->float
template<int EPI, typename OutT>
__global__ void __launch_bounds__(512, 1)
hgemm192b(const __half* __restrict__ A, const __half* __restrict__ Bm, OutT* __restrict__ C,
          int K, int lda, int ldb, int ldc,
          const float* __restrict__ bias, const float* __restrict__ resid)
{
    extern __shared__ char smem[];
    const uint32_t sbase = smem_u32(smem);

    int tid = threadIdx.x;
    int warp = tid >> 5, lane = tid & 31;
    int wm = warp >> 2, wn = warp & 3;     // 4x4 warps, 32x48 warp tile
    int rowBlk = blockIdx.y * 128;
    int colBlk = blockIdx.x * 192;

    float acc[2][6][4];
    #pragma unroll
    for (int mi = 0; mi < 2; mi++)
        #pragma unroll
        for (int ni = 0; ni < 6; ni++)
            #pragma unroll
            for (int r = 0; r < 4; r++) acc[mi][ni][r] = 0.0f;

    uint32_t aoff = (uint32_t)(((wm*32 + (lane & 15)) * 72 + ((lane >> 4) << 3)) * 2);
    uint32_t boff = (uint32_t)(((wn*48 + (lane & 7) + ((lane >> 4) << 3)) * 72 + (lane & 8)) * 2);

    auto load_chunk = [&](int ck, int s) {
        uint32_t ab = sbase + s*STG4;
        uint32_t bb = ab + A4SZ;
        const __half* Ag = A + (long)rowBlk * lda + ck*64;
        const __half* Bg = Bm + (long)colBlk * ldb + ck*64;
        #pragma unroll
        for (int it = 0; it < 2; it++) {           // A: 1024 granules = 2*512
            int idx = tid + it*512;
            int row = idx >> 3, gq = idx & 7;
            cpa16(ab + row*144 + gq*16, Ag + (long)row*lda + gq*8);
        }
        #pragma unroll
        for (int it = 0; it < 3; it++) {           // B: 1536 granules = 3*512
            int idx = tid + it*512;
            int row = idx >> 3, gq = idx & 7;
            cpa16(bb + row*144 + gq*16, Bg + (long)row*ldb + gq*8);
        }
        cp_commit();
    };

    int nc = K >> 6;
    load_chunk(0, 0);
    if (nc > 1) load_chunk(1, 1); else cp_commit();
    if (nc > 2) load_chunk(2, 2); else cp_commit();

    for (int c = 0; c < nc; c++) {
        cp_wait<2>();
        __syncthreads();
        if (c + 3 < nc) load_chunk(c + 3, (c + 3) & 3);
        else            cp_commit();

        uint32_t As = sbase + (c & 3)*STG4;
        uint32_t Bs = As + A4SZ;

        uint32_t af[2][2][4], bf[2][3][4];
        #pragma unroll
        for (int mi = 0; mi < 2; mi++) ldsm_x4(af[0][mi], As + aoff + mi*2304u);
        #pragma unroll
        for (int j = 0; j < 3; j++)    ldsm_x4(bf[0][j],  Bs + boff + j*2304u);

        #pragma unroll
        for (int ki = 0; ki < 4; ki++) {
            int cur = ki & 1;
            if (ki < 3) {
                int kk2 = (ki + 1) * 32;
                #pragma unroll
                for (int mi = 0; mi < 2; mi++) ldsm_x4(af[cur^1][mi], As + aoff + mi*2304u + kk2);
                #pragma unroll
                for (int j = 0; j < 3; j++)    ldsm_x4(bf[cur^1][j],  Bs + boff + j*2304u + kk2);
            }
            #pragma unroll
            for (int mi = 0; mi < 2; mi++)
                #pragma unroll
                for (int ni = 0; ni < 6; ni++)
                    mma_f16(acc[mi][ni], af[cur][mi][0], af[cur][mi][1],
                            af[cur][mi][2], af[cur][mi][3],
                            bf[cur][ni >> 1][(ni & 1)*2], bf[cur][ni >> 1][(ni & 1)*2 + 1]);
        }
    }

    __syncthreads();
    int g = lane >> 2, t4 = lane & 3;
    #pragma unroll
    for (int mi = 0; mi < 2; mi++) {
        #pragma unroll
        for (int ni = 0; ni < 6; ni++) {
            int r0 = rowBlk + wm*32 + mi*16 + g;
            int c0 = colBlk + wn*48 + ni*8 + 2*t4;
            float v0 = acc[mi][ni][0], v1 = acc[mi][ni][1];
            float v2 = acc[mi][ni][2], v3 = acc[mi][ni][3];
            float b0 = bias[c0], b1 = bias[c0+1];
            v0 += b0; v1 += b1; v2 += b0; v3 += b1;
            if (EPI == 2) {
                v0 = gelu_exact(v0); v1 = gelu_exact(v1);
                v2 = gelu_exact(v2); v3 = gelu_exact(v3);
            }
            if (EPI == 3) {
                const float2 ra = *(const float2*)&resid[(long)r0*ldc + c0];
                const float2 rb = *(const float2*)&resid[(long)(r0+8)*ldc + c0];
                v0 += ra.x; v1 += ra.y; v2 += rb.x; v3 += rb.y;
            }
            if (EPI == 2) {
                *(__half2*)&((__half*)C)[(long)r0*ldc + c0]     = __floats2half2_rn(v0, v1);
                *(__half2*)&((__half*)C)[(long)(r0+8)*ldc + c0] = __floats2half2_rn(v2, v3);
            } else {
                *(float2*)&((float*)C)[(long)r0*ldc + c0]     = make_float2(v0, v1);
                *(float2*)&((float*)C)[(long)(r0+8)*ldc + c0] = make_float2(v2, v3);
            }
        }
    }
}

// ---------------- fast transpose fp32 -> fp16, half2 stores ----------------
__global__ void transpose_h2(const float* __restrict__ src, __half* __restrict__ dst,
                             int Rr, int Ccol)
{
    __shared__ float t[64][33];
    int c0 = blockIdx.x * 32, r0 = blockIdx.y * 64;
    int tx = threadIdx.x, ty = threadIdx.y;
    int x = c0 + tx;
    #pragma unroll
    for (int j = ty; j < 64; j += 8)
        t[j][tx] = src[(long)(r0 + j) * Ccol + x];
    __syncthreads();
    #pragma unroll
    for (int j = ty; j < 32; j += 8) {
        __half2 h = __floats2half2_rn(t[2*tx][j], t[2*tx+1][j]);
        *(__half2*)&dst[(long)(c0 + j) * Rr + r0 + 2*tx] = h;
    }
}

// ---------------- fused conv QKV, 4-position register blocking ----------------
__global__ void __launch_bounds__(256, 2) conv_qkv(const float* __restrict__ x,
                                                   const float* __restrict__ qw,
                                                   const float* __restrict__ kw,
                                                   const float* __restrict__ vw)
{
    __shared__ float sp[3][P_+2][P_+2];
    __shared__ float swq[81], swk[81], swv[81];
    int tid = threadIdx.x;
    int patch = blockIdx.x;
    int b = patch >> 8;
    int n = patch & 255;
    const float* xp = x + (long)patch * C_;

    if (tid < 81) { swq[tid] = qw[tid]; swk[tid] = kw[tid]; swv[tid] = vw[tid]; }
    for (int i = tid; i < 3*(P_+2)*(P_+2); i += 256)
        ((float*)sp)[i] = 0.0f;
    __syncthreads();
    {
        const float4* xp4 = (const float4*)xp;
        #pragma unroll
        for (int it = 0; it < 3; it++) {
            int i4 = tid + it*256;
            float4 v = xp4[i4];
            int i = i4 * 4;
            int ch = i >> 10;
            int s  = i & 1023;
            int yy = s >> 5, xx = s & 31;
            sp[ch][yy+1][xx+1] = v.x;
            sp[ch][yy+1][xx+2] = v.y;
            sp[ch][yy+1][xx+3] = v.z;
            sp[ch][yy+1][xx+4] = v.w;
        }
    }
    __syncthreads();

    int pos0 = tid * 4;
    int yy = pos0 >> 5, xx = pos0 & 31;
    float aq[3][4], ak[3][4], av[3][4];
    #pragma unroll
    for (int o = 0; o < 3; o++)
        #pragma unroll
        for (int p = 0; p < 4; p++) { aq[o][p] = 0.f; ak[o][p] = 0.f; av[o][p] = 0.f; }

    #pragma unroll
    for (int i = 0; i < 3; i++) {
        #pragma unroll
        for (int dy = 0; dy < 3; dy++) {
            float r[6];
            #pragma unroll
            for (int t = 0; t < 6; t++) r[t] = sp[i][yy+dy][xx+t];
            #pragma unroll
            for (int dx = 0; dx < 3; dx++) {
                int wi = i*9 + dy*3 + dx;
                float wq0 = swq[wi], wq1 = swq[27+wi], wq2 = swq[54+wi];
                float wk0 = swk[wi], wk1 = swk[27+wi], wk2 = swk[54+wi];
                float wv0 = swv[wi], wv1 = swv[27+wi], wv2 = swv[54+wi];
                #pragma unroll
                for (int p = 0; p < 4; p++) {
                    float val = r[dx + p];
                    aq[0][p] = fmaf(val, wq0, aq[0][p]);
                    aq[1][p] = fmaf(val, wq1, aq[1][p]);
                    aq[2][p] = fmaf(val, wq2, aq[2][p]);
                    ak[0][p] = fmaf(val, wk0, ak[0][p]);
                    ak[1][p] = fmaf(val, wk1, ak[1][p]);
                    ak[2][p] = fmaf(val, wk2, ak[2][p]);
                    av[0][p] = fmaf(val, wv0, av[0][p]);
                    av[1][p] = fmaf(val, wv1, av[1][p]);
                    av[2][p] = fmaf(val, wv2, av[2][p]);
                }
            }
        }
    }

    #pragma unroll
    for (int o = 0; o < 3; o++) {
        int c0 = o*1024 + pos0;
        int h = c0 / HD_;
        int d = c0 - h*HD_;
        long bh = (long)(b*H_ + h);
        long base = (bh*N_ + n)*HD_ + d;
        *(__half2*)&g_hq[base]   = __floats2half2_rn(aq[o][0], aq[o][1]);
        *(__half2*)&g_hq[base+2] = __floats2half2_rn(aq[o][2], aq[o][3]);
        *(__half2*)&g_hk[base]   = __floats2half2_rn(ak[o][0], ak[o][1]);
        *(__half2*)&g_hk[base+2] = __floats2half2_rn(ak[o][2], ak[o][3]);
        #pragma unroll
        for (int p = 0; p < 4; p++)
            g_hvt[(bh*HD_ + d + p)*N_ + n] = __float2half_rn(av[o][p]);
    }
}

// ---------------- fused softmax + re-attention + BN -> fp16 ----------------
__global__ void __launch_bounds__(256) softmax_reatten(
    const float* __restrict__ attn, __half* __restrict__ attn2,
    const float* __restrict__ w,  const float* __restrict__ rb,
    const float* __restrict__ g,  const float* __restrict__ bta,
    const float* __restrict__ mean, const float* __restrict__ var)
{
    __shared__ float sp[8][256];
    __shared__ float sw[64], sscale[8], sshift[8];
    int tid = threadIdx.x;
    int h = tid >> 5, lane = tid & 31;
    if (tid < 64) sw[tid] = w[tid];
    if (tid < 8) {
        float inv = rsqrtf(var[tid] + 1e-5f);
        float gi = g[tid] * inv;
        sscale[tid] = gi;
        sshift[tid] = bta[tid] + (rb[tid] - mean[tid]) * gi;
    }
    int b = blockIdx.x >> 8, n = blockIdx.x & 255;
    const float scale = 0.051031036307982884f;
    const float* row = attn + (((long)(b*H_ + h))*N_ + n)*N_;

    float v[8];
    #pragma unroll
    for (int j = 0; j < 8; j++) v[j] = row[lane + j*32] * scale;
    float m = v[0];
    #pragma unroll
    for (int j = 1; j < 8; j++) m = fmaxf(m, v[j]);
    #pragma unroll
    for (int o = 16; o > 0; o >>= 1) m = fmaxf(m, __shfl_xor_sync(0xffffffffu, m, o));
    float s = 0.0f;
    float e[8];
    #pragma unroll
    for (int j = 0; j < 8; j++) { e[j] = __expf(v[j] - m); s += e[j]; }
    #pragma unroll
    for (int o = 16; o > 0; o >>= 1) s += __shfl_xor_sync(0xffffffffu, s, o);
    float inv = 1.0f / s;
    #pragma unroll
    for (int j = 0; j < 8; j++) sp[h][lane + j*32] = e[j] * inv;
    __syncthreads();

    float in[8];
    #pragma unroll
    for (int i = 0; i < 8; i++) in[i] = sp[i][tid];
    #pragma unroll
    for (int o = 0; o < 8; o++) {
        float acc = 0.0f;
        #pragma unroll
        for (int i = 0; i < 8; i++) acc = fmaf(sw[o*8 + i], in[i], acc);
        attn2[(((long)(b*H_ + o))*N_ + n)*N_ + tid] =
            __float2half_rn(acc * sscale[o] + sshift[o]);
    }
}

// ---------------- LayerNorm: two-level stats ----------------
__global__ void ln_part(const float* __restrict__ y)
{
    __shared__ double rs[8], rq[8];
    int b = blockIdx.y, seg = blockIdx.x;
    const float4* p = (const float4*)(y + (long)b * NC_ + (long)seg * (NC_/32));
    double s = 0.0, q = 0.0;
    for (int i = threadIdx.x; i < NC_/128; i += 256) {
        float4 v = p[i];
        s += (double)v.x + (double)v.y + (double)v.z + (double)v.w;
        q += (double)v.x*v.x + (double)v.y*v.y + (double)v.z*v.z + (double)v.w*v.w;
    }
    #pragma unroll
    for (int o = 16; o > 0; o >>= 1) {
        s += __shfl_xor_sync(0xffffffffu, s, o);
        q += __shfl_xor_sync(0xffffffffu, q, o);
    }
    int lane = threadIdx.x & 31, wid = threadIdx.x >> 5;
    if (lane == 0) { rs[wid] = s; rq[wid] = q; }
    __syncthreads();
    if (threadIdx.x == 0) {
        double S = 0.0, Q = 0.0;
        #pragma unroll
        for (int i = 0; i < 8; i++) { S += rs[i]; Q += rq[i]; }
        g_part[(b*32 + seg)*2]     = S;
        g_part[(b*32 + seg)*2 + 1] = Q;
    }
}

__global__ void ln_fin(float* __restrict__ stats)
{
    int b = blockIdx.x, t = threadIdx.x;
    double s = g_part[(b*32 + t)*2];
    double q = g_part[(b*32 + t)*2 + 1];
    #pragma unroll
    for (int o = 16; o > 0; o >>= 1) {
        s += __shfl_xor_sync(0xffffffffu, s, o);
        q += __shfl_xor_sync(0xffffffffu, q, o);
    }
    if (t == 0) {
        double mu  = s / (double)NC_;
        double var = q / (double)NC_ - mu * mu;
        stats[b*2]   = (float)mu;
        stats[b*2+1] = (float)rsqrt(var + 1e-5);
    }
}

__global__ void ln_apply_dual(const float* __restrict__ y, const float* __restrict__ stats,
                              const float* __restrict__ g, const float* __restrict__ beta,
                              float* __restrict__ outf, __half* __restrict__ outh)
{
    long i4 = (long)blockIdx.x * blockDim.x + threadIdx.x;
    long i = i4 * 4;
    int b = (int)(i / NC_);
    int r = (int)(i % NC_);
    float mu = stats[b*2], iv = stats[b*2+1];
    float4 yv = *(const float4*)&y[i];
    const float4 gv = *(const float4*)&g[r];
    const float4 bv = *(const float4*)&beta[r];
    float4 o;
    o.x = (yv.x - mu) * iv * gv.x + bv.x;
    o.y = (yv.y - mu) * iv * gv.y + bv.y;
    o.z = (yv.z - mu) * iv * gv.z + bv.z;
    o.w = (yv.w - mu) * iv * gv.w + bv.w;
    *(float4*)&outf[i] = o;
    __half2 h0 = __floats2half2_rn(o.x, o.y);
    __half2 h1 = __floats2half2_rn(o.z, o.w);
    *(__half2*)&outh[i]   = h0;
    *(__half2*)&outh[i+2] = h1;
}

__global__ void ln_apply(const float* __restrict__ y, const float* __restrict__ stats,
                         const float* __restrict__ g, const float* __restrict__ beta,
                         float* __restrict__ out)
{
    long i4 = (long)blockIdx.x * blockDim.x + threadIdx.x;
    long i = i4 * 4;
    int b = (int)(i / NC_);
    int r = (int)(i % NC_);
    float mu = stats[b*2], iv = stats[b*2+1];
    float4 yv = *(const float4*)&y[i];
    const float4 gv = *(const float4*)&g[r];
    const float4 bv = *(const float4*)&beta[r];
    float4 o;
    o.x = (yv.x - mu) * iv * gv.x + bv.x;
    o.y = (yv.y - mu) * iv * gv.y + bv.y;
    o.z = (yv.z - mu) * iv * gv.z + bv.z;
    o.w = (yv.w - mu) * iv * gv.w + bv.w;
    *(float4*)&out[i] = o;
}

// ---------------- launch ----------------
extern "C" void kernel_launch(void* const* d_in, const int* in_sizes, int n_in,
                              void* d_out, int out_size)
{
    const float* x        = (const float*)d_in[0];
    const float* qconv_w  = (const float*)d_in[1];
    const float* kconv_w  = (const float*)d_in[2];
    const float* vconv_w  = (const float*)d_in[3];
    const float* reat_w   = (const float*)d_in[4];
    const float* reat_b   = (const float*)d_in[5];
    const float* bn_gamma = (const float*)d_in[6];
    const float* bn_beta  = (const float*)d_in[7];
    const float* bn_mean  = (const float*)d_in[8];
    const float* bn_var   = (const float*)d_in[9];
    const float* proj_w   = (const float*)d_in[10];
    const float* proj_b   = (const float*)d_in[11];
    const float* ln_g     = (const float*)d_in[12];
    const float* ln_b     = (const float*)d_in[13];
    const float* ff_w1    = (const float*)d_in[14];
    const float* ff_b1    = (const float*)d_in[15];
    const float* ff_w2    = (const float*)d_in[16];
    const float* ff_b2    = (const float*)d_in[17];
    float* out = (float*)d_out;

    __half *pq, *pk, *pvt, *pattn2, *pctx, *pynh, *ph, *pprojT, *pw1T, *pw2T;
    float *pattn, *py1, *pyn, *py2, *pstats;
    cudaGetSymbolAddress((void**)&pq,     g_hq);
    cudaGetSymbolAddress((void**)&pk,     g_hk);
    cudaGetSymbolAddress((void**)&pvt,    g_hvt);
    cudaGetSymbolAddress((void**)&pattn2, g_hattn2);
    cudaGetSymbolAddress((void**)&pctx,   g_hctx);
    cudaGetSymbolAddress((void**)&pynh,   g_hynh);
    cudaGetSymbolAddress((void**)&ph,     g_hh);
    cudaGetSymbolAddress((void**)&pprojT, g_hprojT);
    cudaGetSymbolAddress((void**)&pw1T,   g_hw1T);
    cudaGetSymbolAddress((void**)&pw2T,   g_hw2T);
    cudaGetSymbolAddress((void**)&pattn,  g_attn);
    cudaGetSymbolAddress((void**)&py1,    g_y1);
    cudaGetSymbolAddress((void**)&pyn,    g_yn);
    cudaGetSymbolAddress((void**)&py2,    g_y2);
    cudaGetSymbolAddress((void**)&pstats, g_stats);

    cudaFuncSetAttribute(hgemm256<1,float>,   cudaFuncAttributeMaxDynamicSharedMemorySize, SMEM2);
    cudaFuncSetAttribute(hgemm192<0,__half>,  cudaFuncAttributeMaxDynamicSharedMemorySize, SMEM4);
    cudaFuncSetAttribute(hgemm192b<2,__half>, cudaFuncAttributeMaxDynamicSharedMemorySize, SMEM4);
    cudaFuncSetAttribute(hgemm192b<3,float>,  cudaFuncAttributeMaxDynamicSharedMemorySize, SMEM4);

    // 1. fused conv QKV  (launch 0)
    conv_qkv<<<B_*N_, 256>>>(x, qconv_w, kconv_w, vconv_w);

    // 2. S = Q K^T  (launch 1)
    hgemm256<1,float><<<dim3(1,2,BH_), 512, SMEM2>>>(pq, pk, pattn,
        HD_, HD_, HD_, N_, (long)N_*HD_, (long)N_*HD_, 1, 65536L, 0L, nullptr, nullptr);

    // 3. fused softmax + re-attention (launch 2)
    softmax_reatten<<<B_*N_, 256>>>(pattn, pattn2, reat_w, reat_b,
                                    bn_gamma, bn_beta, bn_mean, bn_var);

    // 4. ctx = attn2 @ V (launch 3)
    hgemm192<0,__half><<<dim3(2,2,BH_), 384, SMEM4>>>(pattn2, pvt, pctx,
        N_, N_, N_, C_, 65536L, (long)HD_*N_, H_, (long)N_*C_, (long)HD_, nullptr, nullptr);

    // 5. proj weight transpose (launch 4)
    {
        dim3 blk(32, 8);
        transpose_h2<<<dim3(C_/32, C_/64), blk>>>(proj_w, pprojT, C_, C_);
    }

    // 6. y1 = x + ctx @ proj_w + proj_b  (launch 5 — ncu target)
    hgemm192b<3,float><<<dim3(C_/192, (B_*N_)/128), 512, SMEM4>>>(pctx, pprojT, py1,
        C_, C_, C_, C_, proj_b, x);

    // 7. FFN weight transposes
    {
        dim3 blk(32, 8);
        transpose_h2<<<dim3(FF_/32, C_/64), blk>>>(ff_w1, pw1T, C_, FF_);
        transpose_h2<<<dim3(C_/32, FF_/64), blk>>>(ff_w2, pw2T, FF_, C_);
    }

    // 8. LN1
    ln_part<<<dim3(32, B_), 256>>>(py1);
    ln_fin<<<B_, 32>>>(pstats);
    ln_apply_dual<<<QKV_SZ/1024, 256>>>(py1, pstats, ln_g, ln_b, pyn, pynh);

    // 9. h = gelu(yn @ ff_w1 + b1)
    hgemm192b<2,__half><<<dim3(FF_/192, (B_*N_)/128), 512, SMEM4>>>(pynh, pw1T, ph,
        C_, C_, C_, FF_, ff_b1, nullptr);

    // 10. y2 = yn + h @ ff_w2 + b2
    hgemm192b<3,float><<<dim3(C_/192, (B_*N_)/128), 512, SMEM4>>>(ph, pw2T, py2,
        FF_, FF_, FF_, C_, ff_b2, pyn);

    // 11. LN2 -> out
    ln_part<<<dim3(32, B_), 256>>>(py2);
    ln_fin<<<B_, 32>>>(pstats);
    ln_apply<<<QKV_SZ/1024, 256>>>(py2, pstats, ln_g, ln_b, out);
}

// round 15
// speedup vs baseline: 1.4289x; 1.0561x over previous
#include <cuda_runtime.h>
#include <cuda_fp16.h>
#include <math.h>
#include <stdint.h>

// ---------------- problem constants ----------------
#define B_   8
#define N_   256
#define C_   3072
#define H_   8
#define HD_  384
#define FF_  12288
#define P_   32
#define NC_  (N_*C_)
#define BH_  (B_*H_)
#define QKV_SZ   (B_*N_*C_)
#define ATT_SZ   (B_*H_*N_*N_)
#define HBUF_SZ  (B_*N_*FF_)

// ---------------- device scratch ----------------
__device__ __align__(256) __half g_hq[QKV_SZ];
__device__ __align__(256) __half g_hk[QKV_SZ];
__device__ __align__(256) __half g_hvt[QKV_SZ];     // V^T: (BH, hd, N)
__device__ __align__(256) __half g_hattn2[ATT_SZ];
__device__ __align__(256) __half g_hctx[QKV_SZ];
__device__ __align__(256) __half g_hynh[QKV_SZ];
__device__ __align__(256) __half g_hh[HBUF_SZ];
__device__ __align__(256) __half g_hprojW[C_*C_];          // proj_w fp16 row-major [K][N]
__device__ __align__(256) __half g_hw1[(long)C_*FF_];      // ff_w1 fp16 [K][N]
__device__ __align__(256) __half g_hw2[(long)C_*FF_];      // ff_w2 fp16 [K][N]
__device__ float g_attn[ATT_SZ];
__device__ float g_y1[QKV_SZ];
__device__ float g_yn[QKV_SZ];
__device__ float g_y2[QKV_SZ];
__device__ double g_part[B_*32*2];

// ---------------- helpers ----------------
__device__ __forceinline__ float gelu_exact(float x) {
    return 0.5f * x * (1.0f + erff(x * 0.70710678118654752f));
}
__device__ __forceinline__ uint32_t smem_u32(const void* p) {
    return (uint32_t)__cvta_generic_to_shared(p);
}
__device__ __forceinline__ void cpa16(uint32_t dst, const void* src) {
    asm volatile("cp.async.cg.shared.global [%0], [%1], 16;\n" :: "r"(dst), "l"(src));
}
__device__ __forceinline__ void cp_commit() { asm volatile("cp.async.commit_group;\n"); }
template<int NN> __device__ __forceinline__ void cp_wait() {
    asm volatile("cp.async.wait_group %0;\n" :: "n"(NN));
}
__device__ __forceinline__ void ldsm_x4(uint32_t* r, uint32_t addr) {
    asm volatile("ldmatrix.sync.aligned.m8n8.x4.shared.b16 {%0,%1,%2,%3}, [%4];"
                 : "=r"(r[0]), "=r"(r[1]), "=r"(r[2]), "=r"(r[3]) : "r"(addr));
}
__device__ __forceinline__ void ldsm_x4_t(uint32_t* r, uint32_t addr) {
    asm volatile("ldmatrix.sync.aligned.m8n8.x4.trans.shared.b16 {%0,%1,%2,%3}, [%4];"
                 : "=r"(r[0]), "=r"(r[1]), "=r"(r[2]), "=r"(r[3]) : "r"(addr));
}
__device__ __forceinline__ void mma_f16(float c[4], uint32_t a0, uint32_t a1, uint32_t a2,
                                        uint32_t a3, uint32_t b0, uint32_t b1) {
    asm volatile(
        "mma.sync.aligned.m16n8k16.row.col.f32.f16.f16.f32 "
        "{%0,%1,%2,%3},{%4,%5,%6,%7},{%8,%9},{%0,%1,%2,%3};\n"
        : "+f"(c[0]), "+f"(c[1]), "+f"(c[2]), "+f"(c[3])
        : "r"(a0), "r"(a1), "r"(a2), "r"(a3), "r"(b0), "r"(b1));
}

// ================= 128x256 fp16 GEMM, 512 threads, 4-stage (QK) =================
#define A2SZ (128*144)
#define B2SZ (256*144)
#define STG2 (A2SZ + B2SZ)    // 55296
#define SMEM2 (4*STG2)        // 221184

template<int EPI, typename OutT>
__global__ void __launch_bounds__(512, 1)
hgemm256(const __half* __restrict__ A, const __half* __restrict__ Bm, OutT* __restrict__ C,
         int K, int lda, int ldb, int ldc,
         long sA, long sB, int zdiv, long sC1, long sC2,
         const float* __restrict__ bias, const float* __restrict__ resid)
{
    extern __shared__ char smem[];
    const uint32_t sbase = smem_u32(smem);

    int tid = threadIdx.x;
    int warp = tid >> 5, lane = tid & 31;
    int wm = warp >> 2, wn = warp & 3;
    int z = blockIdx.z;
    const __half* Ab = A + (long)z * sA;
    const __half* Bb = Bm + (long)z * sB;
    long coff = (long)(z / zdiv) * sC1 + (long)(z % zdiv) * sC2;
    OutT* Cb = C + coff;
    int rowBlk = blockIdx.y * 128;
    int colBlk = blockIdx.x * 256;

    float acc[2][8][4];
    #pragma unroll
    for (int mi = 0; mi < 2; mi++)
        #pragma unroll
        for (int ni = 0; ni < 8; ni++)
            #pragma unroll
            for (int r = 0; r < 4; r++) acc[mi][ni][r] = 0.0f;

    uint32_t aoff = (uint32_t)(((wm*32 + (lane & 15)) * 72 + ((lane >> 4) << 3)) * 2);
    uint32_t boff = (uint32_t)(((wn*64 + (lane & 7) + ((lane >> 4) << 3)) * 72 + (lane & 8)) * 2);

    auto load_chunk = [&](int ck, int s) {
        uint32_t ab = sbase + s*STG2;
        uint32_t bb = ab + A2SZ;
        const __half* Ag = Ab + (long)rowBlk * lda + ck*64;
        const __half* Bg = Bb + (long)colBlk * ldb + ck*64;
        #pragma unroll
        for (int it = 0; it < 2; it++) {
            int idx = tid + it*512;
            int row = idx >> 3, gq = idx & 7;
            cpa16(ab + row*144 + gq*16, Ag + (long)row*lda + gq*8);
        }
        #pragma unroll
        for (int it = 0; it < 4; it++) {
            int idx = tid + it*512;
            int row = idx >> 3, gq = idx & 7;
            cpa16(bb + row*144 + gq*16, Bg + (long)row*ldb + gq*8);
        }
        cp_commit();
    };

    int nc = K >> 6;
    load_chunk(0, 0);
    if (nc > 1) load_chunk(1, 1); else cp_commit();
    if (nc > 2) load_chunk(2, 2); else cp_commit();

    for (int c = 0; c < nc; c++) {
        cp_wait<2>();
        __syncthreads();
        if (c + 3 < nc) load_chunk(c + 3, (c + 3) & 3);
        else            cp_commit();

        uint32_t As = sbase + (c & 3)*STG2;
        uint32_t Bs = As + A2SZ;

        uint32_t af[2][2][4], bf[2][4][4];
        #pragma unroll
        for (int mi = 0; mi < 2; mi++) ldsm_x4(af[0][mi], As + aoff + mi*2304u);
        #pragma unroll
        for (int j = 0; j < 4; j++)    ldsm_x4(bf[0][j],  Bs + boff + j*2304u);

        #pragma unroll
        for (int ki = 0; ki < 4; ki++) {
            int cur = ki & 1;
            if (ki < 3) {
                int kk2 = (ki + 1) * 16 * 2;
                #pragma unroll
                for (int mi = 0; mi < 2; mi++) ldsm_x4(af[cur^1][mi], As + aoff + mi*2304u + kk2);
                #pragma unroll
                for (int j = 0; j < 4; j++)    ldsm_x4(bf[cur^1][j],  Bs + boff + j*2304u + kk2);
            }
            #pragma unroll
            for (int mi = 0; mi < 2; mi++)
                #pragma unroll
                for (int ni = 0; ni < 8; ni++)
                    mma_f16(acc[mi][ni], af[cur][mi][0], af[cur][mi][1],
                            af[cur][mi][2], af[cur][mi][3],
                            bf[cur][ni >> 1][(ni & 1)*2], bf[cur][ni >> 1][(ni & 1)*2 + 1]);
        }
    }

    __syncthreads();
    int g = lane >> 2, t4 = lane & 3;
    #pragma unroll
    for (int mi = 0; mi < 2; mi++) {
        #pragma unroll
        for (int ni = 0; ni < 8; ni++) {
            int r0 = rowBlk + wm*32 + mi*16 + g;
            int c0 = colBlk + wn*64 + ni*8 + 2*t4;
            float v0 = acc[mi][ni][0], v1 = acc[mi][ni][1];
            float v2 = acc[mi][ni][2], v3 = acc[mi][ni][3];
            if (EPI == 0 || EPI == 2) {
                *(__half2*)&((__half*)Cb)[(long)r0*ldc + c0]     = __floats2half2_rn(v0, v1);
                *(__half2*)&((__half*)Cb)[(long)(r0+8)*ldc + c0] = __floats2half2_rn(v2, v3);
            } else {
                *(float2*)&((float*)Cb)[(long)r0*ldc + c0]     = make_float2(v0, v1);
                *(float2*)&((float*)Cb)[(long)(r0+8)*ldc + c0] = make_float2(v2, v3);
            }
        }
    }
}

// ================= 128x192 fp16 GEMM, 384 threads, 4-stage (AV, B n-major) =================
#define A4SZ (128*144)        // 18432
#define B4SZ (192*144)        // 27648
#define STG4 (A4SZ + B4SZ)    // 46080
#define SMEM4 (4*STG4)        // 184320

template<int EPI, typename OutT>
__global__ void __launch_bounds__(384, 1)
hgemm192(const __half* __restrict__ A, const __half* __restrict__ Bm, OutT* __restrict__ C,
         int K, int lda, int ldb, int ldc,
         long sA, long sB, int zdiv, long sC1, long sC2,
         const float* __restrict__ bias, const float* __restrict__ resid)
{
    extern __shared__ char smem[];
    const uint32_t sbase = smem_u32(smem);

    int tid = threadIdx.x;
    int warp = tid >> 5, lane = tid & 31;
    int wm = warp / 3, wn = warp % 3;      // 4x3 warp grid, 32x64 warp tile
    int z = blockIdx.z;
    const __half* Ab = A + (long)z * sA;
    const __half* Bb = Bm + (long)z * sB;
    long coff = (long)(z / zdiv) * sC1 + (long)(z % zdiv) * sC2;
    OutT* Cb = C + coff;
    int rowBlk = blockIdx.y * 128;
    int colBlk = blockIdx.x * 192;

    float acc[2][8][4];
    #pragma unroll
    for (int mi = 0; mi < 2; mi++)
        #pragma unroll
        for (int ni = 0; ni < 8; ni++)
            #pragma unroll
            for (int r = 0; r < 4; r++) acc[mi][ni][r] = 0.0f;

    uint32_t aoff = (uint32_t)(((wm*32 + (lane & 15)) * 72 + ((lane >> 4) << 3)) * 2);
    uint32_t boff = (uint32_t)(((wn*64 + (lane & 7) + ((lane >> 4) << 3)) * 72 + (lane & 8)) * 2);

    auto load_chunk = [&](int ck, int s) {
        uint32_t ab = sbase + s*STG4;
        uint32_t bb = ab + A4SZ;
        const __half* Ag = Ab + (long)rowBlk * lda + ck*64;
        const __half* Bg = Bb + (long)colBlk * ldb + ck*64;
        #pragma unroll
        for (int it = 0; it < 3; it++) {
            int idx = tid + it*384;
            if (idx < 1024) {
                int row = idx >> 3, gq = idx & 7;
                cpa16(ab + row*144 + gq*16, Ag + (long)row*lda + gq*8);
            }
        }
        #pragma unroll
        for (int it = 0; it < 4; it++) {
            int idx = tid + it*384;
            int row = idx >> 3, gq = idx & 7;
            cpa16(bb + row*144 + gq*16, Bg + (long)row*ldb + gq*8);
        }
        cp_commit();
    };

    int nc = K >> 6;
    load_chunk(0, 0);
    if (nc > 1) load_chunk(1, 1); else cp_commit();
    if (nc > 2) load_chunk(2, 2); else cp_commit();

    for (int c = 0; c < nc; c++) {
        cp_wait<2>();
        __syncthreads();
        if (c + 3 < nc) load_chunk(c + 3, (c + 3) & 3);
        else            cp_commit();

        uint32_t As = sbase + (c & 3)*STG4;
        uint32_t Bs = As + A4SZ;

        uint32_t af[2][2][4], bf[2][4][4];
        #pragma unroll
        for (int mi = 0; mi < 2; mi++) ldsm_x4(af[0][mi], As + aoff + mi*2304u);
        #pragma unroll
        for (int j = 0; j < 4; j++)    ldsm_x4(bf[0][j],  Bs + boff + j*2304u);

        #pragma unroll
        for (int ki = 0; ki < 4; ki++) {
            int cur = ki & 1;
            if (ki < 3) {
                int kk2 = (ki + 1) * 32;
                #pragma unroll
                for (int mi = 0; mi < 2; mi++) ldsm_x4(af[cur^1][mi], As + aoff + mi*2304u + kk2);
                #pragma unroll
                for (int j = 0; j < 4; j++)    ldsm_x4(bf[cur^1][j],  Bs + boff + j*2304u + kk2);
            }
            #pragma unroll
            for (int mi = 0; mi < 2; mi++)
                #pragma unroll
                for (int ni = 0; ni < 8; ni++)
                    mma_f16(acc[mi][ni], af[cur][mi][0], af[cur][mi][1],
                            af[cur][mi][2], af[cur][mi][3],
                            bf[cur][ni >> 1][(ni & 1)*2], bf[cur][ni >> 1][(ni & 1)*2 + 1]);
        }
    }

    __syncthreads();
    int g = lane >> 2, t4 = lane & 3;
    #pragma unroll
    for (int mi = 0; mi < 2; mi++) {
        #pragma unroll
        for (int ni = 0; ni < 8; ni++) {
            int r0 = rowBlk + wm*32 + mi*16 + g;
            int c0 = colBlk + wn*64 + ni*8 + 2*t4;
            float v0 = acc[mi][ni][0], v1 = acc[mi][ni][1];
            float v2 = acc[mi][ni][2], v3 = acc[mi][ni][3];
            *(__half2*)&((__half*)Cb)[(long)r0*ldc + c0]     = __floats2half2_rn(v0, v1);
            *(__half2*)&((__half*)Cb)[(long)(r0+8)*ldc + c0] = __floats2half2_rn(v2, v3);
        }
    }
}

// ======== 128x192 fp16 GEMM, 384 threads, 4-stage, B ROW-MAJOR [K][N] (ldsm.trans) ========
#define B4TSZ (64*400)         // 25600 (row stride 400B, conflict-free for ldsm phases)
#define STG4T (A4SZ + B4TSZ)   // 44032
#define SMEM4T (4*STG4T)       // 176128

// EPI: 2 bias+gelu->half, 3 bias+resid->float
template<int EPI, typename OutT>
__global__ void __launch_bounds__(384, 1)
hgemm192t(const __half* __restrict__ A, const __half* __restrict__ Bm, OutT* __restrict__ C,
          int K, int lda, int ldb, int ldc,
          const float* __restrict__ bias, const float* __restrict__ resid)
{
    extern __shared__ char smem[];
    const uint32_t sbase = smem_u32(smem);

    int tid = threadIdx.x;
    int warp = tid >> 5, lane = tid & 31;
    int wm = warp / 3, wn = warp % 3;      // 4x3 warp grid, 32x64 warp tile
    int rowBlk = blockIdx.y * 128;
    int colBlk = blockIdx.x * 192;

    float acc[2][8][4];
    #pragma unroll
    for (int mi = 0; mi < 2; mi++)
        #pragma unroll
        for (int ni = 0; ni < 8; ni++)
            #pragma unroll
            for (int r = 0; r < 4; r++) acc[mi][ni][r] = 0.0f;

    uint32_t aoff = (uint32_t)(((wm*32 + (lane & 15)) * 72 + ((lane >> 4) << 3)) * 2);
    // trans-B: lanes 0-15 -> k-rows 0-15, lanes 16-31 -> same k at n+8
    uint32_t bofft = (uint32_t)((lane & 15) * 400 + (wn*64 + ((lane >> 4) << 3)) * 2);

    auto load_chunk = [&](int ck, int s) {
        uint32_t ab = sbase + s*STG4T;
        uint32_t bb = ab + A4SZ;
        const __half* Ag = A + (long)rowBlk * lda + ck*64;
        #pragma unroll
        for (int it = 0; it < 3; it++) {           // A: 1024 granules
            int idx = tid + it*384;
            if (idx < 1024) {
                int row = idx >> 3, gq = idx & 7;
                cpa16(ab + row*144 + gq*16, Ag + (long)row*lda + gq*8);
            }
        }
        #pragma unroll
        for (int it = 0; it < 4; it++) {           // B: 64 rows x 24 granules = 1536
            int idx = tid + it*384;
            int row = idx / 24, gq = idx - row*24;
            cpa16(bb + row*400 + gq*16,
                  Bm + (long)(ck*64 + row)*ldb + colBlk + gq*8);
        }
        cp_commit();
    };

    int nc = K >> 6;
    load_chunk(0, 0);
    if (nc > 1) load_chunk(1, 1); else cp_commit();
    if (nc > 2) load_chunk(2, 2); else cp_commit();

    for (int c = 0; c < nc; c++) {
        cp_wait<2>();
        __syncthreads();
        if (c + 3 < nc) load_chunk(c + 3, (c + 3) & 3);
        else            cp_commit();

        uint32_t As = sbase + (c & 3)*STG4T;
        uint32_t Bs = As + A4SZ;

        uint32_t af[2][2][4], bf[2][4][4];
        #pragma unroll
        for (int mi = 0; mi < 2; mi++) ldsm_x4(af[0][mi], As + aoff + mi*2304u);
        #pragma unroll
        for (int j = 0; j < 4; j++)    ldsm_x4_t(bf[0][j], Bs + bofft + j*32);

        #pragma unroll
        for (int ki = 0; ki < 4; ki++) {
            int cur = ki & 1;
            if (ki < 3) {
                int kk2a = (ki + 1) * 32;         // A: 16 k * 2B
                int kk2b = (ki + 1) * 6400;       // B: 16 k-rows * 400B
                #pragma unroll
                for (int mi = 0; mi < 2; mi++) ldsm_x4(af[cur^1][mi], As + aoff + mi*2304u + kk2a);
                #pragma unroll
                for (int j = 0; j < 4; j++)    ldsm_x4_t(bf[cur^1][j], Bs + bofft + kk2b + j*32);
            }
            #pragma unroll
            for (int mi = 0; mi < 2; mi++)
                #pragma unroll
                for (int ni = 0; ni < 8; ni++)
                    mma_f16(acc[mi][ni], af[cur][mi][0], af[cur][mi][1],
                            af[cur][mi][2], af[cur][mi][3],
                            bf[cur][ni >> 1][(ni & 1)*2], bf[cur][ni >> 1][(ni & 1)*2 + 1]);
        }
    }

    __syncthreads();
    int g = lane >> 2, t4 = lane & 3;
    #pragma unroll
    for (int mi = 0; mi < 2; mi++) {
        #pragma unroll
        for (int ni = 0; ni < 8; ni++) {
            int r0 = rowBlk + wm*32 + mi*16 + g;
            int c0 = colBlk + wn*64 + ni*8 + 2*t4;
            float v0 = acc[mi][ni][0], v1 = acc[mi][ni][1];
            float v2 = acc[mi][ni][2], v3 = acc[mi][ni][3];
            float b0 = bias[c0], b1 = bias[c0+1];
            v0 += b0; v1 += b1; v2 += b0; v3 += b1;
            if (EPI == 2) {
                v0 = gelu_exact(v0); v1 = gelu_exact(v1);
                v2 = gelu_exact(v2); v3 = gelu_exact(v3);
            }
            if (EPI == 3) {
                const float2 ra = *(const float2*)&resid[(long)r0*ldc + c0];
                const float2 rb = *(const float2*)&resid[(long)(r0+8)*ldc + c0];
                v0 += ra.x; v1 += ra.y; v2 += rb.x; v3 += rb.y;
            }
            if (EPI == 2) {
                *(__half2*)&((__half*)C)[(long)r0*ldc + c0]     = __floats2half2_rn(v0, v1);
                *(__half2*)&((__half*)C)[(long)(r0+8)*ldc + c0] = __floats2half2_rn(v2, v3);
            } else {
                *(float2*)&((float*)C)[(long)r0*ldc + c0]     = make_float2(v0, v1);
                *(float2*)&((float*)C)[(long)(r0+8)*ldc + c0] = make_float2(v2, v3);
            }
        }
    }
}

// ---------------- linear fp32 -> fp16 convert ----------------
__global__ void convert_h(const float* __restrict__ src, __half* __restrict__ dst)
{
    long i4 = (long)blockIdx.x * blockDim.x + threadIdx.x;
    float4 v = ((const float4*)src)[i4];
    long i = i4 * 4;
    *(__half2*)&dst[i]   = __floats2half2_rn(v.x, v.y);
    *(__half2*)&dst[i+2] = __floats2half2_rn(v.z, v.w);
}

// ---------------- fused conv QKV, 4-position register blocking ----------------
__global__ void __launch_bounds__(256, 2) conv_qkv(const float* __restrict__ x,
                                                   const float* __restrict__ qw,
                                                   const float* __restrict__ kw,
                                                   const float* __restrict__ vw)
{
    __shared__ float sp[3][P_+2][P_+2];
    __shared__ float swq[81], swk[81], swv[81];
    int tid = threadIdx.x;
    int patch = blockIdx.x;
    int b = patch >> 8;
    int n = patch & 255;
    const float* xp = x + (long)patch * C_;

    if (tid < 81) { swq[tid] = qw[tid]; swk[tid] = kw[tid]; swv[tid] = vw[tid]; }
    for (int i = tid; i < 3*(P_+2)*(P_+2); i += 256)
        ((float*)sp)[i] = 0.0f;
    __syncthreads();
    {
        const float4* xp4 = (const float4*)xp;
        #pragma unroll
        for (int it = 0; it < 3; it++) {
            int i4 = tid + it*256;
            float4 v = xp4[i4];
            int i = i4 * 4;
            int ch = i >> 10;
            int s  = i & 1023;
            int yy = s >> 5, xx = s & 31;
            sp[ch][yy+1][xx+1] = v.x;
            sp[ch][yy+1][xx+2] = v.y;
            sp[ch][yy+1][xx+3] = v.z;
            sp[ch][yy+1][xx+4] = v.w;
        }
    }
    __syncthreads();

    int pos0 = tid * 4;
    int yy = pos0 >> 5, xx = pos0 & 31;
    float aq[3][4], ak[3][4], av[3][4];
    #pragma unroll
    for (int o = 0; o < 3; o++)
        #pragma unroll
        for (int p = 0; p < 4; p++) { aq[o][p] = 0.f; ak[o][p] = 0.f; av[o][p] = 0.f; }

    #pragma unroll
    for (int i = 0; i < 3; i++) {
        #pragma unroll
        for (int dy = 0; dy < 3; dy++) {
            float r[6];
            #pragma unroll
            for (int t = 0; t < 6; t++) r[t] = sp[i][yy+dy][xx+t];
            #pragma unroll
            for (int dx = 0; dx < 3; dx++) {
                int wi = i*9 + dy*3 + dx;
                float wq0 = swq[wi], wq1 = swq[27+wi], wq2 = swq[54+wi];
                float wk0 = swk[wi], wk1 = swk[27+wi], wk2 = swk[54+wi];
                float wv0 = swv[wi], wv1 = swv[27+wi], wv2 = swv[54+wi];
                #pragma unroll
                for (int p = 0; p < 4; p++) {
                    float val = r[dx + p];
                    aq[0][p] = fmaf(val, wq0, aq[0][p]);
                    aq[1][p] = fmaf(val, wq1, aq[1][p]);
                    aq[2][p] = fmaf(val, wq2, aq[2][p]);
                    ak[0][p] = fmaf(val, wk0, ak[0][p]);
                    ak[1][p] = fmaf(val, wk1, ak[1][p]);
                    ak[2][p] = fmaf(val, wk2, ak[2][p]);
                    av[0][p] = fmaf(val, wv0, av[0][p]);
                    av[1][p] = fmaf(val, wv1, av[1][p]);
                    av[2][p] = fmaf(val, wv2, av[2][p]);
                }
            }
        }
    }

    #pragma unroll
    for (int o = 0; o < 3; o++) {
        int c0 = o*1024 + pos0;
        int h = c0 / HD_;
        int d = c0 - h*HD_;
        long bh = (long)(b*H_ + h);
        long base = (bh*N_ + n)*HD_ + d;
        *(__half2*)&g_hq[base]   = __floats2half2_rn(aq[o][0], aq[o][1]);
        *(__half2*)&g_hq[base+2] = __floats2half2_rn(aq[o][2], aq[o][3]);
        *(__half2*)&g_hk[base]   = __floats2half2_rn(ak[o][0], ak[o][1]);
        *(__half2*)&g_hk[base+2] = __floats2half2_rn(ak[o][2], ak[o][3]);
        #pragma unroll
        for (int p = 0; p < 4; p++)
            g_hvt[(bh*HD_ + d + p)*N_ + n] = __float2half_rn(av[o][p]);
    }
}

// ---------------- fused softmax + re-attention + BN -> fp16 ----------------
__global__ void __launch_bounds__(256) softmax_reatten(
    const float* __restrict__ attn, __half* __restrict__ attn2,
    const float* __restrict__ w,  const float* __restrict__ rb,
    const float* __restrict__ g,  const float* __restrict__ bta,
    const float* __restrict__ mean, const float* __restrict__ var)
{
    __shared__ float sp[8][256];
    __shared__ float sw[64], sscale[8], sshift[8];
    int tid = threadIdx.x;
    int h = tid >> 5, lane = tid & 31;
    if (tid < 64) sw[tid] = w[tid];
    if (tid < 8) {
        float inv = rsqrtf(var[tid] + 1e-5f);
        float gi = g[tid] * inv;
        sscale[tid] = gi;
        sshift[tid] = bta[tid] + (rb[tid] - mean[tid]) * gi;
    }
    int b = blockIdx.x >> 8, n = blockIdx.x & 255;
    const float scale = 0.051031036307982884f;
    const float* row = attn + (((long)(b*H_ + h))*N_ + n)*N_;

    float v[8];
    #pragma unroll
    for (int j = 0; j < 8; j++) v[j] = row[lane + j*32] * scale;
    float m = v[0];
    #pragma unroll
    for (int j = 1; j < 8; j++) m = fmaxf(m, v[j]);
    #pragma unroll
    for (int o = 16; o > 0; o >>= 1) m = fmaxf(m, __shfl_xor_sync(0xffffffffu, m, o));
    float s = 0.0f;
    float e[8];
    #pragma unroll
    for (int j = 0; j < 8; j++) { e[j] = __expf(v[j] - m); s += e[j]; }
    #pragma unroll
    for (int o = 16; o > 0; o >>= 1) s += __shfl_xor_sync(0xffffffffu, s, o);
    float inv = 1.0f / s;
    #pragma unroll
    for (int j = 0; j < 8; j++) sp[h][lane + j*32] = e[j] * inv;
    __syncthreads();

    float in[8];
    #pragma unroll
    for (int i = 0; i < 8; i++) in[i] = sp[i][tid];
    #pragma unroll
    for (int o = 0; o < 8; o++) {
        float acc = 0.0f;
        #pragma unroll
        for (int i = 0; i < 8; i++) acc = fmaf(sw[o*8 + i], in[i], acc);
        attn2[(((long)(b*H_ + o))*N_ + n)*N_ + tid] =
            __float2half_rn(acc * sscale[o] + sshift[o]);
    }
}

// ---------------- LayerNorm: partial stats ----------------
__global__ void ln_part(const float* __restrict__ y)
{
    __shared__ double rs[8], rq[8];
    int b = blockIdx.y, seg = blockIdx.x;
    const float4* p = (const float4*)(y + (long)b * NC_ + (long)seg * (NC_/32));
    double s = 0.0, q = 0.0;
    for (int i = threadIdx.x; i < NC_/128; i += 256) {
        float4 v = p[i];
        s += (double)v.x + (double)v.y + (double)v.z + (double)v.w;
        q += (double)v.x*v.x + (double)v.y*v.y + (double)v.z*v.z + (double)v.w*v.w;
    }
    #pragma unroll
    for (int o = 16; o > 0; o >>= 1) {
        s += __shfl_xor_sync(0xffffffffu, s, o);
        q += __shfl_xor_sync(0xffffffffu, q, o);
    }
    int lane = threadIdx.x & 31, wid = threadIdx.x >> 5;
    if (lane == 0) { rs[wid] = s; rq[wid] = q; }
    __syncthreads();
    if (threadIdx.x == 0) {
        double S = 0.0, Q = 0.0;
        #pragma unroll
        for (int i = 0; i < 8; i++) { S += rs[i]; Q += rq[i]; }
        g_part[(b*32 + seg)*2]     = S;
        g_part[(b*32 + seg)*2 + 1] = Q;
    }
}

// LN apply with inline final reduce (all block elems share one batch b)
__global__ void ln_apply_dual(const float* __restrict__ y,
                              const float* __restrict__ g, const float* __restrict__ beta,
                              float* __restrict__ outf, __half* __restrict__ outh)
{
    __shared__ float smu, siv;
    long i4 = (long)blockIdx.x * blockDim.x + threadIdx.x;
    long i = i4 * 4;
    int b = (int)(i / NC_);
    if (threadIdx.x < 32) {
        double s = g_part[(b*32 + threadIdx.x)*2];
        double q = g_part[(b*32 + threadIdx.x)*2 + 1];
        #pragma unroll
        for (int o = 16; o > 0; o >>= 1) {
            s += __shfl_xor_sync(0xffffffffu, s, o);
            q += __shfl_xor_sync(0xffffffffu, q, o);
        }
        if (threadIdx.x == 0) {
            double mu  = s / (double)NC_;
            double var = q / (double)NC_ - mu * mu;
            smu = (float)mu;
            siv = (float)rsqrt(var + 1e-5);
        }
    }
    __syncthreads();
    int r = (int)(i % NC_);
    float mu = smu, iv = siv;
    float4 yv = *(const float4*)&y[i];
    const float4 gv = *(const float4*)&g[r];
    const float4 bv = *(const float4*)&beta[r];
    float4 o;
    o.x = (yv.x - mu) * iv * gv.x + bv.x;
    o.y = (yv.y - mu) * iv * gv.y + bv.y;
    o.z = (yv.z - mu) * iv * gv.z + bv.z;
    o.w = (yv.w - mu) * iv * gv.w + bv.w;
    *(float4*)&outf[i] = o;
    *(__half2*)&outh[i]   = __floats2half2_rn(o.x, o.y);
    *(__half2*)&outh[i+2] = __floats2half2_rn(o.z, o.w);
}

__global__ void ln_apply(const float* __restrict__ y,
                         const float* __restrict__ g, const float* __restrict__ beta,
                         float* __restrict__ out)
{
    __shared__ float smu, siv;
    long i4 = (long)blockIdx.x * blockDim.x + threadIdx.x;
    long i = i4 * 4;
    int b = (int)(i / NC_);
    if (threadIdx.x < 32) {
        double s = g_part[(b*32 + threadIdx.x)*2];
        double q = g_part[(b*32 + threadIdx.x)*2 + 1];
        #pragma unroll
        for (int o = 16; o > 0; o >>= 1) {
            s += __shfl_xor_sync(0xffffffffu, s, o);
            q += __shfl_xor_sync(0xffffffffu, q, o);
        }
        if (threadIdx.x == 0) {
            double mu  = s / (double)NC_;
            double var = q / (double)NC_ - mu * mu;
            smu = (float)mu;
            siv = (float)rsqrt(var + 1e-5);
        }
    }
    __syncthreads();
    int r = (int)(i % NC_);
    float mu = smu, iv = siv;
    float4 yv = *(const float4*)&y[i];
    const float4 gv = *(const float4*)&g[r];
    const float4 bv = *(const float4*)&beta[r];
    float4 o;
    o.x = (yv.x - mu) * iv * gv.x + bv.x;
    o.y = (yv.y - mu) * iv * gv.y + bv.y;
    o.z = (yv.z - mu) * iv * gv.z + bv.z;
    o.w = (yv.w - mu) * iv * gv.w + bv.w;
    *(float4*)&out[i] = o;
}

// ---------------- launch ----------------
extern "C" void kernel_launch(void* const* d_in, const int* in_sizes, int n_in,
                              void* d_out, int out_size)
{
    const float* x        = (const float*)d_in[0];
    const float* qconv_w  = (const float*)d_in[1];
    const float* kconv_w  = (const float*)d_in[2];
    const float* vconv_w  = (const float*)d_in[3];
    const float* reat_w   = (const float*)d_in[4];
    const float* reat_b   = (const float*)d_in[5];
    const float* bn_gamma = (const float*)d_in[6];
    const float* bn_beta  = (const float*)d_in[7];
    const float* bn_mean  = (const float*)d_in[8];
    const float* bn_var   = (const float*)d_in[9];
    const float* proj_w   = (const float*)d_in[10];
    const float* proj_b   = (const float*)d_in[11];
    const float* ln_g     = (const float*)d_in[12];
    const float* ln_b     = (const float*)d_in[13];
    const float* ff_w1    = (const float*)d_in[14];
    const float* ff_b1    = (const float*)d_in[15];
    const float* ff_w2    = (const float*)d_in[16];
    const float* ff_b2    = (const float*)d_in[17];
    float* out = (float*)d_out;

    __half *pq, *pk, *pvt, *pattn2, *pctx, *pynh, *ph, *pprojW, *pw1, *pw2;
    float *pattn, *py1, *pyn, *py2;
    cudaGetSymbolAddress((void**)&pq,     g_hq);
    cudaGetSymbolAddress((void**)&pk,     g_hk);
    cudaGetSymbolAddress((void**)&pvt,    g_hvt);
    cudaGetSymbolAddress((void**)&pattn2, g_hattn2);
    cudaGetSymbolAddress((void**)&pctx,   g_hctx);
    cudaGetSymbolAddress((void**)&pynh,   g_hynh);
    cudaGetSymbolAddress((void**)&ph,     g_hh);
    cudaGetSymbolAddress((void**)&pprojW, g_hprojW);
    cudaGetSymbolAddress((void**)&pw1,    g_hw1);
    cudaGetSymbolAddress((void**)&pw2,    g_hw2);
    cudaGetSymbolAddress((void**)&pattn,  g_attn);
    cudaGetSymbolAddress((void**)&py1,    g_y1);
    cudaGetSymbolAddress((void**)&pyn,    g_yn);
    cudaGetSymbolAddress((void**)&py2,    g_y2);

    cudaFuncSetAttribute(hgemm256<1,float>,   cudaFuncAttributeMaxDynamicSharedMemorySize, SMEM2);
    cudaFuncSetAttribute(hgemm192<0,__half>,  cudaFuncAttributeMaxDynamicSharedMemorySize, SMEM4);
    cudaFuncSetAttribute(hgemm192t<2,__half>, cudaFuncAttributeMaxDynamicSharedMemorySize, SMEM4T);
    cudaFuncSetAttribute(hgemm192t<3,float>,  cudaFuncAttributeMaxDynamicSharedMemorySize, SMEM4T);

    // 1. fused conv QKV  (launch 0)
    conv_qkv<<<B_*N_, 256>>>(x, qconv_w, kconv_w, vconv_w);

    // 2. S = Q K^T  (launch 1)
    hgemm256<1,float><<<dim3(1,2,BH_), 512, SMEM2>>>(pq, pk, pattn,
        HD_, HD_, HD_, N_, (long)N_*HD_, (long)N_*HD_, 1, 65536L, 0L, nullptr, nullptr);

    // 3. fused softmax + re-attention (launch 2)
    softmax_reatten<<<B_*N_, 256>>>(pattn, pattn2, reat_w, reat_b,
                                    bn_gamma, bn_beta, bn_mean, bn_var);

    // 4. ctx = attn2 @ V (launch 3)
    hgemm192<0,__half><<<dim3(2,2,BH_), 384, SMEM4>>>(pattn2, pvt, pctx,
        N_, N_, N_, C_, 65536L, (long)HD_*N_, H_, (long)N_*C_, (long)HD_, nullptr, nullptr);

    // 5. proj weight convert fp32->fp16 row-major (launch 4)
    convert_h<<<(C_*C_)/1024, 256>>>(proj_w, pprojW);

    // 6. y1 = x + ctx @ proj_w + proj_b  (launch 5 — ncu target)
    // B row-major [K=C][N=C], ldb=C
    hgemm192t<3,float><<<dim3(C_/192, (B_*N_)/128), 384, SMEM4T>>>(pctx, pprojW, py1,
        C_, C_, C_, C_, proj_b, x);

    // 7. FFN weight converts
    convert_h<<<(int)(((long)C_*FF_)/1024), 256>>>(ff_w1, pw1);
    convert_h<<<(int)(((long)C_*FF_)/1024), 256>>>(ff_w2, pw2);

    // 8. LN1
    ln_part<<<dim3(32, B_), 256>>>(py1);
    ln_apply_dual<<<QKV_SZ/1024, 256>>>(py1, ln_g, ln_b, pyn, pynh);

    // 9. h = gelu(yn @ ff_w1 + b1)   B row-major [K=C][N=FF], ldb=FF
    hgemm192t<2,__half><<<dim3(FF_/192, (B_*N_)/128), 384, SMEM4T>>>(pynh, pw1, ph,
        C_, C_, FF_, FF_, ff_b1, nullptr);

    // 10. y2 = yn + h @ ff_w2 + b2   B row-major [K=FF][N=C], ldb=C
    hgemm192t<3,float><<<dim3(C_/192, (B_*N_)/128), 384, SMEM4T>>>(ph, pw2, py2,
        FF_, FF_, C_, C_, ff_b2, pyn);

    // 11. LN2 -> out
    ln_part<<<dim3(32, B_), 256>>>(py2);
    ln_apply<<<QKV_SZ/1024, 256>>>(py2, ln_g, ln_b, out);
}

// round 16
// speedup vs baseline: 1.5497x; 1.0845x over previous
#include <cuda_runtime.h>
#include <cuda_fp16.h>
#include <math.h>
#include <stdint.h>

// ---------------- problem constants ----------------
#define B_   8
#define N_   256
#define C_   3072
#define H_   8
#define HD_  384
#define FF_  12288
#define P_   32
#define NC_  (N_*C_)
#define BH_  (B_*H_)
#define QKV_SZ   (B_*N_*C_)
#define ATT_SZ   (B_*H_*N_*N_)
#define HBUF_SZ  (B_*N_*FF_)

// ---------------- device scratch ----------------
__device__ __align__(256) __half g_hq[QKV_SZ];
__device__ __align__(256) __half g_hk[QKV_SZ];
__device__ __align__(256) __half g_hvt[QKV_SZ];     // V^T: (BH, hd, N)
__device__ __align__(256) __half g_hattn2[ATT_SZ];
__device__ __align__(256) __half g_hctx[QKV_SZ];
__device__ __align__(256) __half g_hynh[QKV_SZ];
__device__ __align__(256) __half g_hh[HBUF_SZ];
__device__ __align__(256) __half g_hprojW[C_*C_];          // proj_w fp16 row-major [K][N]
__device__ __align__(256) __half g_hw1[(long)C_*FF_];      // ff_w1 fp16 [K][N]
__device__ __align__(256) __half g_hw2[(long)C_*FF_];      // ff_w2 fp16 [K][N]
__device__ float g_attn[ATT_SZ];
__device__ float g_y1[QKV_SZ];
__device__ float g_yn[QKV_SZ];
__device__ float g_y2[QKV_SZ];
__device__ double g_sums1[B_*2];      // y1 LN stats (sum, sumsq)
__device__ double g_sums2[B_*2];      // y2 LN stats

// ---------------- helpers ----------------
__device__ __forceinline__ float gelu_exact(float x) {
    return 0.5f * x * (1.0f + erff(x * 0.70710678118654752f));
}
__device__ __forceinline__ uint32_t smem_u32(const void* p) {
    return (uint32_t)__cvta_generic_to_shared(p);
}
__device__ __forceinline__ void cpa16(uint32_t dst, const void* src) {
    asm volatile("cp.async.cg.shared.global [%0], [%1], 16;\n" :: "r"(dst), "l"(src));
}
__device__ __forceinline__ void cp_commit() { asm volatile("cp.async.commit_group;\n"); }
template<int NN> __device__ __forceinline__ void cp_wait() {
    asm volatile("cp.async.wait_group %0;\n" :: "n"(NN));
}
__device__ __forceinline__ void ldsm_x4(uint32_t* r, uint32_t addr) {
    asm volatile("ldmatrix.sync.aligned.m8n8.x4.shared.b16 {%0,%1,%2,%3}, [%4];"
                 : "=r"(r[0]), "=r"(r[1]), "=r"(r[2]), "=r"(r[3]) : "r"(addr));
}
__device__ __forceinline__ void ldsm_x4_t(uint32_t* r, uint32_t addr) {
    asm volatile("ldmatrix.sync.aligned.m8n8.x4.trans.shared.b16 {%0,%1,%2,%3}, [%4];"
                 : "=r"(r[0]), "=r"(r[1]), "=r"(r[2]), "=r"(r[3]) : "r"(addr));
}
__device__ __forceinline__ void mma_f16(float c[4], uint32_t a0, uint32_t a1, uint32_t a2,
                                        uint32_t a3, uint32_t b0, uint32_t b1) {
    asm volatile(
        "mma.sync.aligned.m16n8k16.row.col.f32.f16.f16.f32 "
        "{%0,%1,%2,%3},{%4,%5,%6,%7},{%8,%9},{%0,%1,%2,%3};\n"
        : "+f"(c[0]), "+f"(c[1]), "+f"(c[2]), "+f"(c[3])
        : "r"(a0), "r"(a1), "r"(a2), "r"(a3), "r"(b0), "r"(b1));
}

// ================= 128x256 fp16 GEMM, 512 threads, 4-stage (QK) =================
#define A2SZ (128*144)
#define B2SZ (256*144)
#define STG2 (A2SZ + B2SZ)    // 55296
#define SMEM2 (4*STG2)        // 221184

template<int EPI, typename OutT>
__global__ void __launch_bounds__(512, 1)
hgemm256(const __half* __restrict__ A, const __half* __restrict__ Bm, OutT* __restrict__ C,
         int K, int lda, int ldb, int ldc,
         long sA, long sB, int zdiv, long sC1, long sC2,
         const float* __restrict__ bias, const float* __restrict__ resid)
{
    extern __shared__ char smem[];
    const uint32_t sbase = smem_u32(smem);

    int tid = threadIdx.x;
    int warp = tid >> 5, lane = tid & 31;
    int wm = warp >> 2, wn = warp & 3;
    int z = blockIdx.z;
    const __half* Ab = A + (long)z * sA;
    const __half* Bb = Bm + (long)z * sB;
    long coff = (long)(z / zdiv) * sC1 + (long)(z % zdiv) * sC2;
    OutT* Cb = C + coff;
    int rowBlk = blockIdx.y * 128;
    int colBlk = blockIdx.x * 256;

    float acc[2][8][4];
    #pragma unroll
    for (int mi = 0; mi < 2; mi++)
        #pragma unroll
        for (int ni = 0; ni < 8; ni++)
            #pragma unroll
            for (int r = 0; r < 4; r++) acc[mi][ni][r] = 0.0f;

    uint32_t aoff = (uint32_t)(((wm*32 + (lane & 15)) * 72 + ((lane >> 4) << 3)) * 2);
    uint32_t boff = (uint32_t)(((wn*64 + (lane & 7) + ((lane >> 4) << 3)) * 72 + (lane & 8)) * 2);

    auto load_chunk = [&](int ck, int s) {
        uint32_t ab = sbase + s*STG2;
        uint32_t bb = ab + A2SZ;
        const __half* Ag = Ab + (long)rowBlk * lda + ck*64;
        const __half* Bg = Bb + (long)colBlk * ldb + ck*64;
        #pragma unroll
        for (int it = 0; it < 2; it++) {
            int idx = tid + it*512;
            int row = idx >> 3, gq = idx & 7;
            cpa16(ab + row*144 + gq*16, Ag + (long)row*lda + gq*8);
        }
        #pragma unroll
        for (int it = 0; it < 4; it++) {
            int idx = tid + it*512;
            int row = idx >> 3, gq = idx & 7;
            cpa16(bb + row*144 + gq*16, Bg + (long)row*ldb + gq*8);
        }
        cp_commit();
    };

    int nc = K >> 6;
    load_chunk(0, 0);
    if (nc > 1) load_chunk(1, 1); else cp_commit();
    if (nc > 2) load_chunk(2, 2); else cp_commit();

    for (int c = 0; c < nc; c++) {
        cp_wait<2>();
        __syncthreads();
        if (c + 3 < nc) load_chunk(c + 3, (c + 3) & 3);
        else            cp_commit();

        uint32_t As = sbase + (c & 3)*STG2;
        uint32_t Bs = As + A2SZ;

        uint32_t af[2][2][4], bf[2][4][4];
        #pragma unroll
        for (int mi = 0; mi < 2; mi++) ldsm_x4(af[0][mi], As + aoff + mi*2304u);
        #pragma unroll
        for (int j = 0; j < 4; j++)    ldsm_x4(bf[0][j],  Bs + boff + j*2304u);

        #pragma unroll
        for (int ki = 0; ki < 4; ki++) {
            int cur = ki & 1;
            if (ki < 3) {
                int kk2 = (ki + 1) * 16 * 2;
                #pragma unroll
                for (int mi = 0; mi < 2; mi++) ldsm_x4(af[cur^1][mi], As + aoff + mi*2304u + kk2);
                #pragma unroll
                for (int j = 0; j < 4; j++)    ldsm_x4(bf[cur^1][j],  Bs + boff + j*2304u + kk2);
            }
            #pragma unroll
            for (int mi = 0; mi < 2; mi++)
                #pragma unroll
                for (int ni = 0; ni < 8; ni++)
                    mma_f16(acc[mi][ni], af[cur][mi][0], af[cur][mi][1],
                            af[cur][mi][2], af[cur][mi][3],
                            bf[cur][ni >> 1][(ni & 1)*2], bf[cur][ni >> 1][(ni & 1)*2 + 1]);
        }
    }

    __syncthreads();
    int g = lane >> 2, t4 = lane & 3;
    #pragma unroll
    for (int mi = 0; mi < 2; mi++) {
        #pragma unroll
        for (int ni = 0; ni < 8; ni++) {
            int r0 = rowBlk + wm*32 + mi*16 + g;
            int c0 = colBlk + wn*64 + ni*8 + 2*t4;
            float v0 = acc[mi][ni][0], v1 = acc[mi][ni][1];
            float v2 = acc[mi][ni][2], v3 = acc[mi][ni][3];
            if (EPI == 0 || EPI == 2) {
                *(__half2*)&((__half*)Cb)[(long)r0*ldc + c0]     = __floats2half2_rn(v0, v1);
                *(__half2*)&((__half*)Cb)[(long)(r0+8)*ldc + c0] = __floats2half2_rn(v2, v3);
            } else {
                *(float2*)&((float*)Cb)[(long)r0*ldc + c0]     = make_float2(v0, v1);
                *(float2*)&((float*)Cb)[(long)(r0+8)*ldc + c0] = make_float2(v2, v3);
            }
        }
    }
}

// ================= 128x192 fp16 GEMM, 384 threads, 4-stage (AV, B n-major) =================
#define A4SZ (128*144)        // 18432
#define B4SZ (192*144)        // 27648
#define STG4 (A4SZ + B4SZ)    // 46080
#define SMEM4 (4*STG4)        // 184320

template<int EPI, typename OutT>
__global__ void __launch_bounds__(384, 1)
hgemm192(const __half* __restrict__ A, const __half* __restrict__ Bm, OutT* __restrict__ C,
         int K, int lda, int ldb, int ldc,
         long sA, long sB, int zdiv, long sC1, long sC2,
         const float* __restrict__ bias, const float* __restrict__ resid)
{
    extern __shared__ char smem[];
    const uint32_t sbase = smem_u32(smem);

    int tid = threadIdx.x;
    int warp = tid >> 5, lane = tid & 31;
    int wm = warp / 3, wn = warp % 3;      // 4x3 warp grid, 32x64 warp tile
    int z = blockIdx.z;
    const __half* Ab = A + (long)z * sA;
    const __half* Bb = Bm + (long)z * sB;
    long coff = (long)(z / zdiv) * sC1 + (long)(z % zdiv) * sC2;
    OutT* Cb = C + coff;
    int rowBlk = blockIdx.y * 128;
    int colBlk = blockIdx.x * 192;

    float acc[2][8][4];
    #pragma unroll
    for (int mi = 0; mi < 2; mi++)
        #pragma unroll
        for (int ni = 0; ni < 8; ni++)
            #pragma unroll
            for (int r = 0; r < 4; r++) acc[mi][ni][r] = 0.0f;

    uint32_t aoff = (uint32_t)(((wm*32 + (lane & 15)) * 72 + ((lane >> 4) << 3)) * 2);
    uint32_t boff = (uint32_t)(((wn*64 + (lane & 7) + ((lane >> 4) << 3)) * 72 + (lane & 8)) * 2);

    auto load_chunk = [&](int ck, int s) {
        uint32_t ab = sbase + s*STG4;
        uint32_t bb = ab + A4SZ;
        const __half* Ag = Ab + (long)rowBlk * lda + ck*64;
        const __half* Bg = Bb + (long)colBlk * ldb + ck*64;
        #pragma unroll
        for (int it = 0; it < 3; it++) {
            int idx = tid + it*384;
            if (idx < 1024) {
                int row = idx >> 3, gq = idx & 7;
                cpa16(ab + row*144 + gq*16, Ag + (long)row*lda + gq*8);
            }
        }
        #pragma unroll
        for (int it = 0; it < 4; it++) {
            int idx = tid + it*384;
            int row = idx >> 3, gq = idx & 7;
            cpa16(bb + row*144 + gq*16, Bg + (long)row*ldb + gq*8);
        }
        cp_commit();
    };

    int nc = K >> 6;
    load_chunk(0, 0);
    if (nc > 1) load_chunk(1, 1); else cp_commit();
    if (nc > 2) load_chunk(2, 2); else cp_commit();

    for (int c = 0; c < nc; c++) {
        cp_wait<2>();
        __syncthreads();
        if (c + 3 < nc) load_chunk(c + 3, (c + 3) & 3);
        else            cp_commit();

        uint32_t As = sbase + (c & 3)*STG4;
        uint32_t Bs = As + A4SZ;

        uint32_t af[2][2][4], bf[2][4][4];
        #pragma unroll
        for (int mi = 0; mi < 2; mi++) ldsm_x4(af[0][mi], As + aoff + mi*2304u);
        #pragma unroll
        for (int j = 0; j < 4; j++)    ldsm_x4(bf[0][j],  Bs + boff + j*2304u);

        #pragma unroll
        for (int ki = 0; ki < 4; ki++) {
            int cur = ki & 1;
            if (ki < 3) {
                int kk2 = (ki + 1) * 32;
                #pragma unroll
                for (int mi = 0; mi < 2; mi++) ldsm_x4(af[cur^1][mi], As + aoff + mi*2304u + kk2);
                #pragma unroll
                for (int j = 0; j < 4; j++)    ldsm_x4(bf[cur^1][j],  Bs + boff + j*2304u + kk2);
            }
            #pragma unroll
            for (int mi = 0; mi < 2; mi++)
                #pragma unroll
                for (int ni = 0; ni < 8; ni++)
                    mma_f16(acc[mi][ni], af[cur][mi][0], af[cur][mi][1],
                            af[cur][mi][2], af[cur][mi][3],
                            bf[cur][ni >> 1][(ni & 1)*2], bf[cur][ni >> 1][(ni & 1)*2 + 1]);
        }
    }

    __syncthreads();
    int g = lane >> 2, t4 = lane & 3;
    #pragma unroll
    for (int mi = 0; mi < 2; mi++) {
        #pragma unroll
        for (int ni = 0; ni < 8; ni++) {
            int r0 = rowBlk + wm*32 + mi*16 + g;
            int c0 = colBlk + wn*64 + ni*8 + 2*t4;
            float v0 = acc[mi][ni][0], v1 = acc[mi][ni][1];
            float v2 = acc[mi][ni][2], v3 = acc[mi][ni][3];
            *(__half2*)&((__half*)Cb)[(long)r0*ldc + c0]     = __floats2half2_rn(v0, v1);
            *(__half2*)&((__half*)Cb)[(long)(r0+8)*ldc + c0] = __floats2half2_rn(v2, v3);
        }
    }
}

// ======== 128x192 fp16 GEMM, 384 threads, 4-stage, B ROW-MAJOR [K][N] (ldsm.trans) ========
#define B4TSZ (64*400)         // 25600
#define STG4T (A4SZ + B4TSZ)   // 44032
#define SMEM4T (4*STG4T)       // 176128

// EPI: 2 bias+gelu->half, 3 bias+resid->float (+LN stats accum into sums)
template<int EPI, typename OutT>
__global__ void __launch_bounds__(384, 1)
hgemm192t(const __half* __restrict__ A, const __half* __restrict__ Bm, OutT* __restrict__ C,
          int K, int lda, int ldb, int ldc,
          const float* __restrict__ bias, const float* __restrict__ resid,
          double* __restrict__ sums)
{
    extern __shared__ char smem[];
    const uint32_t sbase = smem_u32(smem);

    int tid = threadIdx.x;
    int warp = tid >> 5, lane = tid & 31;
    int wm = warp / 3, wn = warp % 3;
    int rowBlk = blockIdx.y * 128;
    int colBlk = blockIdx.x * 192;

    float acc[2][8][4];
    #pragma unroll
    for (int mi = 0; mi < 2; mi++)
        #pragma unroll
        for (int ni = 0; ni < 8; ni++)
            #pragma unroll
            for (int r = 0; r < 4; r++) acc[mi][ni][r] = 0.0f;

    uint32_t aoff = (uint32_t)(((wm*32 + (lane & 15)) * 72 + ((lane >> 4) << 3)) * 2);
    uint32_t bofft = (uint32_t)((lane & 15) * 400 + (wn*64 + ((lane >> 4) << 3)) * 2);

    auto load_chunk = [&](int ck, int s) {
        uint32_t ab = sbase + s*STG4T;
        uint32_t bb = ab + A4SZ;
        const __half* Ag = A + (long)rowBlk * lda + ck*64;
        #pragma unroll
        for (int it = 0; it < 3; it++) {
            int idx = tid + it*384;
            if (idx < 1024) {
                int row = idx >> 3, gq = idx & 7;
                cpa16(ab + row*144 + gq*16, Ag + (long)row*lda + gq*8);
            }
        }
        #pragma unroll
        for (int it = 0; it < 4; it++) {
            int idx = tid + it*384;
            int row = idx / 24, gq = idx - row*24;
            cpa16(bb + row*400 + gq*16,
                  Bm + (long)(ck*64 + row)*ldb + colBlk + gq*8);
        }
        cp_commit();
    };

    int nc = K >> 6;
    load_chunk(0, 0);
    if (nc > 1) load_chunk(1, 1); else cp_commit();
    if (nc > 2) load_chunk(2, 2); else cp_commit();

    for (int c = 0; c < nc; c++) {
        cp_wait<2>();
        __syncthreads();
        if (c + 3 < nc) load_chunk(c + 3, (c + 3) & 3);
        else            cp_commit();

        uint32_t As = sbase + (c & 3)*STG4T;
        uint32_t Bs = As + A4SZ;

        uint32_t af[2][2][4], bf[2][4][4];
        #pragma unroll
        for (int mi = 0; mi < 2; mi++) ldsm_x4(af[0][mi], As + aoff + mi*2304u);
        #pragma unroll
        for (int j = 0; j < 4; j++)    ldsm_x4_t(bf[0][j], Bs + bofft + j*32);

        #pragma unroll
        for (int ki = 0; ki < 4; ki++) {
            int cur = ki & 1;
            if (ki < 3) {
                int kk2a = (ki + 1) * 32;
                int kk2b = (ki + 1) * 6400;
                #pragma unroll
                for (int mi = 0; mi < 2; mi++) ldsm_x4(af[cur^1][mi], As + aoff + mi*2304u + kk2a);
                #pragma unroll
                for (int j = 0; j < 4; j++)    ldsm_x4_t(bf[cur^1][j], Bs + bofft + kk2b + j*32);
            }
            #pragma unroll
            for (int mi = 0; mi < 2; mi++)
                #pragma unroll
                for (int ni = 0; ni < 8; ni++)
                    mma_f16(acc[mi][ni], af[cur][mi][0], af[cur][mi][1],
                            af[cur][mi][2], af[cur][mi][3],
                            bf[cur][ni >> 1][(ni & 1)*2], bf[cur][ni >> 1][(ni & 1)*2 + 1]);
        }
    }

    __syncthreads();
    int g = lane >> 2, t4 = lane & 3;
    float ls = 0.0f, lq = 0.0f;
    #pragma unroll
    for (int mi = 0; mi < 2; mi++) {
        #pragma unroll
        for (int ni = 0; ni < 8; ni++) {
            int r0 = rowBlk + wm*32 + mi*16 + g;
            int c0 = colBlk + wn*64 + ni*8 + 2*t4;
            float v0 = acc[mi][ni][0], v1 = acc[mi][ni][1];
            float v2 = acc[mi][ni][2], v3 = acc[mi][ni][3];
            float b0 = bias[c0], b1 = bias[c0+1];
            v0 += b0; v1 += b1; v2 += b0; v3 += b1;
            if (EPI == 2) {
                v0 = gelu_exact(v0); v1 = gelu_exact(v1);
                v2 = gelu_exact(v2); v3 = gelu_exact(v3);
            }
            if (EPI == 3) {
                const float2 ra = *(const float2*)&resid[(long)r0*ldc + c0];
                const float2 rb = *(const float2*)&resid[(long)(r0+8)*ldc + c0];
                v0 += ra.x; v1 += ra.y; v2 += rb.x; v3 += rb.y;
                ls += v0 + v1 + v2 + v3;
                lq += v0*v0 + v1*v1 + v2*v2 + v3*v3;
            }
            if (EPI == 2) {
                *(__half2*)&((__half*)C)[(long)r0*ldc + c0]     = __floats2half2_rn(v0, v1);
                *(__half2*)&((__half*)C)[(long)(r0+8)*ldc + c0] = __floats2half2_rn(v2, v3);
            } else {
                *(float2*)&((float*)C)[(long)r0*ldc + c0]     = make_float2(v0, v1);
                *(float2*)&((float*)C)[(long)(r0+8)*ldc + c0] = make_float2(v2, v3);
            }
        }
    }

    if (EPI == 3) {
        __shared__ double ss[12], sq[12];
        double ds = (double)ls, dq = (double)lq;
        #pragma unroll
        for (int o = 16; o > 0; o >>= 1) {
            ds += __shfl_xor_sync(0xffffffffu, ds, o);
            dq += __shfl_xor_sync(0xffffffffu, dq, o);
        }
        if (lane == 0) { ss[warp] = ds; sq[warp] = dq; }
        __syncthreads();
        if (tid == 0) {
            double S = 0.0, Q = 0.0;
            #pragma unroll
            for (int i = 0; i < 12; i++) { S += ss[i]; Q += sq[i]; }
            int b = rowBlk >> 8;
            atomicAdd(&sums[b*2],     S);
            atomicAdd(&sums[b*2 + 1], Q);
        }
    }
}

// ---------------- zero LN accumulators ----------------
__global__ void zero_sums()
{
    if (threadIdx.x < B_*2) { g_sums1[threadIdx.x] = 0.0; g_sums2[threadIdx.x] = 0.0; }
}

// ---------------- linear fp32 -> fp16 convert (single) ----------------
__global__ void convert_h(const float* __restrict__ src, __half* __restrict__ dst)
{
    long i4 = (long)blockIdx.x * blockDim.x + threadIdx.x;
    float4 v = ((const float4*)src)[i4];
    long i = i4 * 4;
    *(__half2*)&dst[i]   = __floats2half2_rn(v.x, v.y);
    *(__half2*)&dst[i+2] = __floats2half2_rn(v.z, v.w);
}

// dual convert: blockIdx.y selects (src0->dst0) or (src1->dst1)
__global__ void convert_h2(const float* __restrict__ s0, __half* __restrict__ d0,
                           const float* __restrict__ s1, __half* __restrict__ d1)
{
    const float* src = blockIdx.y ? s1 : s0;
    __half* dst = blockIdx.y ? d1 : d0;
    long i4 = (long)blockIdx.x * blockDim.x + threadIdx.x;
    float4 v = ((const float4*)src)[i4];
    long i = i4 * 4;
    *(__half2*)&dst[i]   = __floats2half2_rn(v.x, v.y);
    *(__half2*)&dst[i+2] = __floats2half2_rn(v.z, v.w);
}

// ---------------- fused conv QKV ----------------
__global__ void __launch_bounds__(256, 2) conv_qkv(const float* __restrict__ x,
                                                   const float* __restrict__ qw,
                                                   const float* __restrict__ kw,
                                                   const float* __restrict__ vw)
{
    __shared__ float sp[3][P_+2][P_+2];
    __shared__ float swq[81], swk[81], swv[81];
    int tid = threadIdx.x;
    int patch = blockIdx.x;
    int b = patch >> 8;
    int n = patch & 255;
    const float* xp = x + (long)patch * C_;

    if (tid < 81) { swq[tid] = qw[tid]; swk[tid] = kw[tid]; swv[tid] = vw[tid]; }
    for (int i = tid; i < 3*(P_+2)*(P_+2); i += 256)
        ((float*)sp)[i] = 0.0f;
    __syncthreads();
    {
        const float4* xp4 = (const float4*)xp;
        #pragma unroll
        for (int it = 0; it < 3; it++) {
            int i4 = tid + it*256;
            float4 v = xp4[i4];
            int i = i4 * 4;
            int ch = i >> 10;
            int s  = i & 1023;
            int yy = s >> 5, xx = s & 31;
            sp[ch][yy+1][xx+1] = v.x;
            sp[ch][yy+1][xx+2] = v.y;
            sp[ch][yy+1][xx+3] = v.z;
            sp[ch][yy+1][xx+4] = v.w;
        }
    }
    __syncthreads();

    int pos0 = tid * 4;
    int yy = pos0 >> 5, xx = pos0 & 31;
    float aq[3][4], ak[3][4], av[3][4];
    #pragma unroll
    for (int o = 0; o < 3; o++)
        #pragma unroll
        for (int p = 0; p < 4; p++) { aq[o][p] = 0.f; ak[o][p] = 0.f; av[o][p] = 0.f; }

    #pragma unroll
    for (int i = 0; i < 3; i++) {
        #pragma unroll
        for (int dy = 0; dy < 3; dy++) {
            float r[6];
            #pragma unroll
            for (int t = 0; t < 6; t++) r[t] = sp[i][yy+dy][xx+t];
            #pragma unroll
            for (int dx = 0; dx < 3; dx++) {
                int wi = i*9 + dy*3 + dx;
                float wq0 = swq[wi], wq1 = swq[27+wi], wq2 = swq[54+wi];
                float wk0 = swk[wi], wk1 = swk[27+wi], wk2 = swk[54+wi];
                float wv0 = swv[wi], wv1 = swv[27+wi], wv2 = swv[54+wi];
                #pragma unroll
                for (int p = 0; p < 4; p++) {
                    float val = r[dx + p];
                    aq[0][p] = fmaf(val, wq0, aq[0][p]);
                    aq[1][p] = fmaf(val, wq1, aq[1][p]);
                    aq[2][p] = fmaf(val, wq2, aq[2][p]);
                    ak[0][p] = fmaf(val, wk0, ak[0][p]);
                    ak[1][p] = fmaf(val, wk1, ak[1][p]);
                    ak[2][p] = fmaf(val, wk2, ak[2][p]);
                    av[0][p] = fmaf(val, wv0, av[0][p]);
                    av[1][p] = fmaf(val, wv1, av[1][p]);
                    av[2][p] = fmaf(val, wv2, av[2][p]);
                }
            }
        }
    }

    #pragma unroll
    for (int o = 0; o < 3; o++) {
        int c0 = o*1024 + pos0;
        int h = c0 / HD_;
        int d = c0 - h*HD_;
        long bh = (long)(b*H_ + h);
        long base = (bh*N_ + n)*HD_ + d;
        *(__half2*)&g_hq[base]   = __floats2half2_rn(aq[o][0], aq[o][1]);
        *(__half2*)&g_hq[base+2] = __floats2half2_rn(aq[o][2], aq[o][3]);
        *(__half2*)&g_hk[base]   = __floats2half2_rn(ak[o][0], ak[o][1]);
        *(__half2*)&g_hk[base+2] = __floats2half2_rn(ak[o][2], ak[o][3]);
        #pragma unroll
        for (int p = 0; p < 4; p++)
            g_hvt[(bh*HD_ + d + p)*N_ + n] = __float2half_rn(av[o][p]);
    }
}

// ---------------- fused softmax + re-attention + BN -> fp16 ----------------
__global__ void __launch_bounds__(256) softmax_reatten(
    const float* __restrict__ attn, __half* __restrict__ attn2,
    const float* __restrict__ w,  const float* __restrict__ rb,
    const float* __restrict__ g,  const float* __restrict__ bta,
    const float* __restrict__ mean, const float* __restrict__ var)
{
    __shared__ float sp[8][256];
    __shared__ float sw[64], sscale[8], sshift[8];
    int tid = threadIdx.x;
    int h = tid >> 5, lane = tid & 31;
    if (tid < 64) sw[tid] = w[tid];
    if (tid < 8) {
        float inv = rsqrtf(var[tid] + 1e-5f);
        float gi = g[tid] * inv;
        sscale[tid] = gi;
        sshift[tid] = bta[tid] + (rb[tid] - mean[tid]) * gi;
    }
    int b = blockIdx.x >> 8, n = blockIdx.x & 255;
    const float scale = 0.051031036307982884f;
    const float* row = attn + (((long)(b*H_ + h))*N_ + n)*N_;

    float v[8];
    #pragma unroll
    for (int j = 0; j < 8; j++) v[j] = row[lane + j*32] * scale;
    float m = v[0];
    #pragma unroll
    for (int j = 1; j < 8; j++) m = fmaxf(m, v[j]);
    #pragma unroll
    for (int o = 16; o > 0; o >>= 1) m = fmaxf(m, __shfl_xor_sync(0xffffffffu, m, o));
    float s = 0.0f;
    float e[8];
    #pragma unroll
    for (int j = 0; j < 8; j++) { e[j] = __expf(v[j] - m); s += e[j]; }
    #pragma unroll
    for (int o = 16; o > 0; o >>= 1) s += __shfl_xor_sync(0xffffffffu, s, o);
    float inv = 1.0f / s;
    #pragma unroll
    for (int j = 0; j < 8; j++) sp[h][lane + j*32] = e[j] * inv;
    __syncthreads();

    float in[8];
    #pragma unroll
    for (int i = 0; i < 8; i++) in[i] = sp[i][tid];
    #pragma unroll
    for (int o = 0; o < 8; o++) {
        float acc = 0.0f;
        #pragma unroll
        for (int i = 0; i < 8; i++) acc = fmaf(sw[o*8 + i], in[i], acc);
        attn2[(((long)(b*H_ + o))*N_ + n)*N_ + tid] =
            __float2half_rn(acc * sscale[o] + sshift[o]);
    }
}

// ---------------- LN apply kernels (stats from fused accumulators) ----------------
__global__ void ln_apply_dual(const float* __restrict__ y, const double* __restrict__ sums,
                              const float* __restrict__ g, const float* __restrict__ beta,
                              float* __restrict__ outf, __half* __restrict__ outh)
{
    __shared__ float smu, siv;
    long i4 = (long)blockIdx.x * blockDim.x + threadIdx.x;
    long i = i4 * 4;
    int b = (int)(i / NC_);
    if (threadIdx.x == 0) {
        double mu  = sums[b*2] / (double)NC_;
        double var = sums[b*2 + 1] / (double)NC_ - mu * mu;
        smu = (float)mu;
        siv = (float)rsqrt(var + 1e-5);
    }
    __syncthreads();
    int r = (int)(i % NC_);
    float mu = smu, iv = siv;
    float4 yv = *(const float4*)&y[i];
    const float4 gv = *(const float4*)&g[r];
    const float4 bv = *(const float4*)&beta[r];
    float4 o;
    o.x = (yv.x - mu) * iv * gv.x + bv.x;
    o.y = (yv.y - mu) * iv * gv.y + bv.y;
    o.z = (yv.z - mu) * iv * gv.z + bv.z;
    o.w = (yv.w - mu) * iv * gv.w + bv.w;
    *(float4*)&outf[i] = o;
    *(__half2*)&outh[i]   = __floats2half2_rn(o.x, o.y);
    *(__half2*)&outh[i+2] = __floats2half2_rn(o.z, o.w);
}

__global__ void ln_apply(const float* __restrict__ y, const double* __restrict__ sums,
                         const float* __restrict__ g, const float* __restrict__ beta,
                         float* __restrict__ out)
{
    __shared__ float smu, siv;
    long i4 = (long)blockIdx.x * blockDim.x + threadIdx.x;
    long i = i4 * 4;
    int b = (int)(i / NC_);
    if (threadIdx.x == 0) {
        double mu  = sums[b*2] / (double)NC_;
        double var = sums[b*2 + 1] / (double)NC_ - mu * mu;
        smu = (float)mu;
        siv = (float)rsqrt(var + 1e-5);
    }
    __syncthreads();
    int r = (int)(i % NC_);
    float mu = smu, iv = siv;
    float4 yv = *(const float4*)&y[i];
    const float4 gv = *(const float4*)&g[r];
    const float4 bv = *(const float4*)&beta[r];
    float4 o;
    o.x = (yv.x - mu) * iv * gv.x + bv.x;
    o.y = (yv.y - mu) * iv * gv.y + bv.y;
    o.z = (yv.z - mu) * iv * gv.z + bv.z;
    o.w = (yv.w - mu) * iv * gv.w + bv.w;
    *(float4*)&out[i] = o;
}

// ---------------- launch ----------------
extern "C" void kernel_launch(void* const* d_in, const int* in_sizes, int n_in,
                              void* d_out, int out_size)
{
    const float* x        = (const float*)d_in[0];
    const float* qconv_w  = (const float*)d_in[1];
    const float* kconv_w  = (const float*)d_in[2];
    const float* vconv_w  = (const float*)d_in[3];
    const float* reat_w   = (const float*)d_in[4];
    const float* reat_b   = (const float*)d_in[5];
    const float* bn_gamma = (const float*)d_in[6];
    const float* bn_beta  = (const float*)d_in[7];
    const float* bn_mean  = (const float*)d_in[8];
    const float* bn_var   = (const float*)d_in[9];
    const float* proj_w   = (const float*)d_in[10];
    const float* proj_b   = (const float*)d_in[11];
    const float* ln_g     = (const float*)d_in[12];
    const float* ln_b     = (const float*)d_in[13];
    const float* ff_w1    = (const float*)d_in[14];
    const float* ff_b1    = (const float*)d_in[15];
    const float* ff_w2    = (const float*)d_in[16];
    const float* ff_b2    = (const float*)d_in[17];
    float* out = (float*)d_out;

    __half *pq, *pk, *pvt, *pattn2, *pctx, *pynh, *ph, *pprojW, *pw1, *pw2;
    float *pattn, *py1, *pyn, *py2;
    double *psum1, *psum2;
    cudaGetSymbolAddress((void**)&pq,     g_hq);
    cudaGetSymbolAddress((void**)&pk,     g_hk);
    cudaGetSymbolAddress((void**)&pvt,    g_hvt);
    cudaGetSymbolAddress((void**)&pattn2, g_hattn2);
    cudaGetSymbolAddress((void**)&pctx,   g_hctx);
    cudaGetSymbolAddress((void**)&pynh,   g_hynh);
    cudaGetSymbolAddress((void**)&ph,     g_hh);
    cudaGetSymbolAddress((void**)&pprojW, g_hprojW);
    cudaGetSymbolAddress((void**)&pw1,    g_hw1);
    cudaGetSymbolAddress((void**)&pw2,    g_hw2);
    cudaGetSymbolAddress((void**)&pattn,  g_attn);
    cudaGetSymbolAddress((void**)&py1,    g_y1);
    cudaGetSymbolAddress((void**)&pyn,    g_yn);
    cudaGetSymbolAddress((void**)&py2,    g_y2);
    cudaGetSymbolAddress((void**)&psum1,  g_sums1);
    cudaGetSymbolAddress((void**)&psum2,  g_sums2);

    cudaFuncSetAttribute(hgemm256<1,float>,   cudaFuncAttributeMaxDynamicSharedMemorySize, SMEM2);
    cudaFuncSetAttribute(hgemm192<0,__half>,  cudaFuncAttributeMaxDynamicSharedMemorySize, SMEM4);
    cudaFuncSetAttribute(hgemm192t<2,__half>, cudaFuncAttributeMaxDynamicSharedMemorySize, SMEM4T);
    cudaFuncSetAttribute(hgemm192t<3,float>,  cudaFuncAttributeMaxDynamicSharedMemorySize, SMEM4T);

    // 0. zero LN accumulators
    zero_sums<<<1, 32>>>();

    // 1. fused conv QKV
    conv_qkv<<<B_*N_, 256>>>(x, qconv_w, kconv_w, vconv_w);

    // 2. S = Q K^T
    hgemm256<1,float><<<dim3(1,2,BH_), 512, SMEM2>>>(pq, pk, pattn,
        HD_, HD_, HD_, N_, (long)N_*HD_, (long)N_*HD_, 1, 65536L, 0L, nullptr, nullptr);

    // 3. fused softmax + re-attention
    softmax_reatten<<<B_*N_, 256>>>(pattn, pattn2, reat_w, reat_b,
                                    bn_gamma, bn_beta, bn_mean, bn_var);

    // 4. ctx = attn2 @ V
    hgemm192<0,__half><<<dim3(2,2,BH_), 384, SMEM4>>>(pattn2, pvt, pctx,
        N_, N_, N_, C_, 65536L, (long)HD_*N_, H_, (long)N_*C_, (long)HD_, nullptr, nullptr);

    // 5. proj weight convert
    convert_h<<<(C_*C_)/1024, 256>>>(proj_w, pprojW);

    // 6. y1 = x + ctx @ proj_w + proj_b  (+ LN1 stats into g_sums1)
    hgemm192t<3,float><<<dim3(C_/192, (B_*N_)/128), 384, SMEM4T>>>(pctx, pprojW, py1,
        C_, C_, C_, C_, proj_b, x, psum1);

    // 7. FFN weight converts (fused dual)
    convert_h2<<<dim3((int)(((long)C_*FF_)/1024), 2), 256>>>(ff_w1, pw1, ff_w2, pw2);

    // 8. LN1 apply
    ln_apply_dual<<<QKV_SZ/1024, 256>>>(py1, psum1, ln_g, ln_b, pyn, pynh);

    // 9. h = gelu(yn @ ff_w1 + b1)
    hgemm192t<2,__half><<<dim3(FF_/192, (B_*N_)/128), 384, SMEM4T>>>(pynh, pw1, ph,
        C_, C_, FF_, FF_, ff_b1, nullptr, nullptr);

    // 10. y2 = yn + h @ ff_w2 + b2  (+ LN2 stats into g_sums2)
    hgemm192t<3,float><<<dim3(C_/192, (B_*N_)/128), 384, SMEM4T>>>(ph, pw2, py2,
        FF_, FF_, C_, C_, ff_b2, pyn, psum2);

    // 11. LN2 apply -> out
    ln_apply<<<QKV_SZ/1024, 256>>>(py2, psum2, ln_g, ln_b, out);
}